// round 1
// baseline (speedup 1.0000x reference)
#include <cuda_runtime.h>

// RBF-kernel causal attention (non-softmax):
//   logit_ij = 2*s*(q_i . k_j) - s*||q_i||^2 - s*||k_j||^2   (j <= i, else masked)
//   out_i = sum_j exp(logit_ij) * v_j
//
// Flash-style tiling, fp32 CUDA-core baseline:
//   grid = (N/64 query tiles, B*H), 256 threads/block, 1 block/SM (113KB smem).
//   Per block: Q tile resident (transposed+swizzled), loop over K/V tiles
//   (causal: only j-tiles <= i-tile), S = Q K^T via 4x4 register micro-tiles,
//   exp+mask, P staged in smem, O += P V via 4x8 micro-tiles.

namespace {
constexpr int NSEQ  = 2048;
constexpr int DDIM  = 128;
constexpr int BM    = 64;
constexpr int BN    = 64;
constexpr int NT    = NSEQ / BM;   // 32 query tiles
constexpr int BHN   = 2 * 16;      // 32 (b,h) pairs
constexpr float SM_SCALE = 0.08838834764831845f;   // 1/sqrt(128)

constexpr int QT_F = DDIM * 64;      // transposed swizzled Q tile
constexpr int KT_F = DDIM * 64;      // transposed swizzled K tile
constexpr int VS_F = BN * DDIM;      // V tile, row-major
constexpr int PS_PITCH = 68;         // P tile pitch (floats), 16B-aligned rows
constexpr int PS_F = BM * PS_PITCH;
constexpr int SMEM_FLOATS = QT_F + KT_F + VS_F + PS_F + BM + BN;
constexpr int SMEM_BYTES  = SMEM_FLOATS * 4;   // 116224 B
}

__global__ __launch_bounds__(256, 1)
void rbf_attn_kernel(const float* __restrict__ gq,
                     const float* __restrict__ gk,
                     const float* __restrict__ gv,
                     float* __restrict__ gout) {
    extern __shared__ float sm[];
    float* Qt  = sm;                 // [d][r] word = d*64 + (r ^ (d & 28))
    float* Kt  = Qt + QT_F;          // same swizzle
    float* Vs  = Kt + KT_F;          // [j][c] linear, pitch 128
    float* Ps  = Vs + VS_F;          // [i][j] pitch 68
    float* qsq = Ps + PS_F;          // SM_SCALE * ||q_i||^2
    float* ksq = qsq + BM;           // SM_SCALE * ||k_j||^2

    const int iq   = blockIdx.x;     // query tile
    const int bh   = blockIdx.y;     // (b,h)
    const int tid  = threadIdx.x;
    const int lane = tid & 31;
    const int warp = tid >> 5;
    const int ty   = tid >> 4;       // 0..15 (row group of 4)
    const int tx   = tid & 15;       // 0..15 (col group)

    const float* qb = gq + (size_t)bh * NSEQ * DDIM;
    const float* kb = gk + (size_t)bh * NSEQ * DDIM;
    const float* vb = gv + (size_t)bh * NSEQ * DDIM;
    float*       ob = gout + (size_t)bh * NSEQ * DDIM;

    // ---- load Q tile transposed+swizzled; qsq via warp reduce ----
    // mapping: f4 = u*256+tid -> row = f4>>5 (uniform per warp), c4 = f4&31
    #pragma unroll
    for (int u = 0; u < 8; u++) {
        int f4  = u * 256 + tid;
        int row = f4 >> 5;
        int c4  = f4 & 31;
        const float4 x = *(const float4*)(qb + (size_t)(iq * BM + row) * DDIM + c4 * 4);
        int d0 = c4 * 4;
        int xr = row ^ (d0 & 28);
        Qt[(d0 + 0) * 64 + xr] = x.x;
        Qt[(d0 + 1) * 64 + xr] = x.y;
        Qt[(d0 + 2) * 64 + xr] = x.z;
        Qt[(d0 + 3) * 64 + xr] = x.w;
        float s2 = x.x * x.x + x.y * x.y + x.z * x.z + x.w * x.w;
        #pragma unroll
        for (int o = 16; o; o >>= 1) s2 += __shfl_xor_sync(0xffffffffu, s2, o);
        if (lane == 0) qsq[row] = SM_SCALE * s2;
    }

    float acc[4][8];
    #pragma unroll
    for (int i = 0; i < 4; i++)
        #pragma unroll
        for (int c = 0; c < 8; c++) acc[i][c] = 0.f;

    const int grow = iq * BM + 4 * ty;

    for (int jt = 0; jt <= iq; jt++) {
        __syncthreads();   // previous iter's PV reads done; (iter 0: Q writes visible after this)

        // ---- load K tile transposed+swizzled (+ksq), V tile linear ----
        #pragma unroll
        for (int u = 0; u < 8; u++) {
            int f4  = u * 256 + tid;
            int row = f4 >> 5;
            int c4  = f4 & 31;
            const float4 x = *(const float4*)(kb + (size_t)(jt * BN + row) * DDIM + c4 * 4);
            int d0 = c4 * 4;
            int xr = row ^ (d0 & 28);
            Kt[(d0 + 0) * 64 + xr] = x.x;
            Kt[(d0 + 1) * 64 + xr] = x.y;
            Kt[(d0 + 2) * 64 + xr] = x.z;
            Kt[(d0 + 3) * 64 + xr] = x.w;
            float s2 = x.x * x.x + x.y * x.y + x.z * x.z + x.w * x.w;
            #pragma unroll
            for (int o = 16; o; o >>= 1) s2 += __shfl_xor_sync(0xffffffffu, s2, o);
            if (lane == 0) ksq[row] = SM_SCALE * s2;

            const float4 xv = *(const float4*)(vb + (size_t)(jt * BN) * DDIM + (size_t)f4 * 4);
            *(float4*)(Vs + f4 * 4) = xv;
        }
        __syncthreads();

        // ---- S = Q K^T (4x4 per thread) ----
        float sacc[4][4];
        #pragma unroll
        for (int i = 0; i < 4; i++)
            #pragma unroll
            for (int j = 0; j < 4; j++) sacc[i][j] = 0.f;

        #pragma unroll 8
        for (int kk = 0; kk < DDIM; kk++) {
            const int xw = kk & 28;
            const float4 a4 = *(const float4*)(Qt + kk * 64 + ((4 * ty) ^ xw));
            const float4 b4 = *(const float4*)(Kt + kk * 64 + ((4 * tx) ^ xw));
            const float av[4] = {a4.x, a4.y, a4.z, a4.w};
            const float bv[4] = {b4.x, b4.y, b4.z, b4.w};
            #pragma unroll
            for (int i = 0; i < 4; i++)
                #pragma unroll
                for (int j = 0; j < 4; j++)
                    sacc[i][j] += av[i] * bv[j];
        }

        // ---- logits -> exp -> mask -> stage P in smem ----
        float qsr[4], ksr[4];
        #pragma unroll
        for (int i = 0; i < 4; i++) qsr[i] = qsq[4 * ty + i];
        #pragma unroll
        for (int j = 0; j < 4; j++) ksr[j] = ksq[4 * tx + j];

        const int  gcol = jt * BN + 4 * tx;
        const bool diag = (jt == iq);
        #pragma unroll
        for (int i = 0; i < 4; i++) {
            float4 pv4;
            float* pp = (float*)&pv4;
            #pragma unroll
            for (int j = 0; j < 4; j++) {
                float lg = (2.f * SM_SCALE) * sacc[i][j] - qsr[i] - ksr[j];
                float p  = __expf(lg);
                if (diag && (gcol + j > grow + i)) p = 0.f;
                pp[j] = p;
            }
            *(float4*)(Ps + (4 * ty + i) * PS_PITCH + 4 * tx) = pv4;
        }
        __syncthreads();

        // ---- O += P V (4x8 per thread) ----
        #pragma unroll 2
        for (int j = 0; j < BN; j++) {
            const float pr[4] = {
                Ps[(4 * ty + 0) * PS_PITCH + j],
                Ps[(4 * ty + 1) * PS_PITCH + j],
                Ps[(4 * ty + 2) * PS_PITCH + j],
                Ps[(4 * ty + 3) * PS_PITCH + j]
            };
            const float4 v0 = *(const float4*)(Vs + j * DDIM + 8 * tx);
            const float4 v1 = *(const float4*)(Vs + j * DDIM + 8 * tx + 4);
            const float vv[8] = {v0.x, v0.y, v0.z, v0.w, v1.x, v1.y, v1.z, v1.w};
            #pragma unroll
            for (int i = 0; i < 4; i++)
                #pragma unroll
                for (int c = 0; c < 8; c++)
                    acc[i][c] += pr[i] * vv[c];
        }
    }

    // ---- epilogue: write O (coalesced float4) ----
    #pragma unroll
    for (int i = 0; i < 4; i++) {
        float* dst = ob + (size_t)(grow + i) * DDIM + 8 * tx;
        *(float4*)(dst)     = make_float4(acc[i][0], acc[i][1], acc[i][2], acc[i][3]);
        *(float4*)(dst + 4) = make_float4(acc[i][4], acc[i][5], acc[i][6], acc[i][7]);
    }
}

extern "C" void kernel_launch(void* const* d_in, const int* in_sizes, int n_in,
                              void* d_out, int out_size) {
    const float* q = (const float*)d_in[0];
    const float* k = (const float*)d_in[1];
    const float* v = (const float*)d_in[2];
    float* out = (float*)d_out;

    cudaFuncSetAttribute(rbf_attn_kernel,
                         cudaFuncAttributeMaxDynamicSharedMemorySize, SMEM_BYTES);

    dim3 grid(NT, BHN);   // x = query tile (fastest -> same-head blocks concurrent, L2 reuse of K/V)
    rbf_attn_kernel<<<grid, 256, SMEM_BYTES>>>(q, k, v, out);
}

// round 3
// speedup vs baseline: 3.3924x; 3.3924x over previous
#include <cuda_runtime.h>
#include <cuda_bf16.h>
#include <cstdint>

// =====================================================================
// RBF-kernel causal attention via legacy mma.sync (HMMA) on sm_103.
//   logit = 2s*(q.k) - s||q||^2 - s||k||^2 ; p = exp(logit), causal ; O = P V
// Split-bf16 (x = hi + lo): every GEMM = 3 bf16 MMAs -> ~fp32 precision.
// CTA: 128 q-rows x 64-kv tiles, 256 threads (8 warps x 16 rows).
//  - Q A-fragments persistent in registers (hi+lo).
//  - K[n][k], Vt as V[j][d] in smem (hi+lo), pitch 272B, ldmatrix.
//  - S accum (16x64/warp) -> exp in regs -> P A-frags in regs (no smem).
//  - O accum (16x128/warp) in regs, written at end.
// =====================================================================

namespace {
constexpr int NSEQ = 2048;
constexpr int DDIM = 128;
constexpr int BM   = 128;
constexpr int BN   = 64;
constexpr float SM_SCALE = 0.08838834764831845f;   // 1/sqrt(128)

constexpr int PITCH = 272;   // bytes per smem tile row (136 bf16): conflict-free
constexpr uint32_t OFF_KHI = 0;
constexpr uint32_t OFF_KLO = OFF_KHI + 64 * PITCH;   // 17408
constexpr uint32_t OFF_VHI = OFF_KLO + 64 * PITCH;
constexpr uint32_t OFF_VLO = OFF_VHI + 64 * PITCH;
constexpr uint32_t OFF_KSQ = OFF_VLO + 64 * PITCH;   // 64 floats
constexpr uint32_t SMEM_BYTES = OFF_KSQ + 256;       // 69888
}

__device__ __forceinline__ uint32_t smem_u32(const void* p) {
    uint32_t a;
    asm("{ .reg .u64 t; cvta.to.shared.u64 t, %1; cvt.u32.u64 %0, t; }"
        : "=r"(a) : "l"(p));
    return a;
}

__device__ __forceinline__ void ldsm_x4(uint32_t* r, uint32_t addr) {
    asm volatile("ldmatrix.sync.aligned.m8n8.x4.shared.b16 {%0,%1,%2,%3}, [%4];"
                 : "=r"(r[0]), "=r"(r[1]), "=r"(r[2]), "=r"(r[3]) : "r"(addr));
}
__device__ __forceinline__ void ldsm_x4_t(uint32_t* r, uint32_t addr) {
    asm volatile("ldmatrix.sync.aligned.m8n8.x4.trans.shared.b16 {%0,%1,%2,%3}, [%4];"
                 : "=r"(r[0]), "=r"(r[1]), "=r"(r[2]), "=r"(r[3]) : "r"(addr));
}
__device__ __forceinline__ void mma_bf16(float* d, const uint32_t* a,
                                         uint32_t b0, uint32_t b1) {
    asm volatile(
        "mma.sync.aligned.m16n8k16.row.col.f32.bf16.bf16.f32 "
        "{%0,%1,%2,%3}, {%4,%5,%6,%7}, {%8,%9}, {%0,%1,%2,%3};"
        : "+f"(d[0]), "+f"(d[1]), "+f"(d[2]), "+f"(d[3])
        : "r"(a[0]), "r"(a[1]), "r"(a[2]), "r"(a[3]), "r"(b0), "r"(b1));
}

// pack (a,b) -> bf16x2 hi word + bf16x2 residual word
__device__ __forceinline__ void split2(float a, float b, uint32_t& hi, uint32_t& lo) {
    __nv_bfloat162 H = __floats2bfloat162_rn(a, b);
    float ra = a - __bfloat162float(H.x);
    float rb = b - __bfloat162float(H.y);
    __nv_bfloat162 L = __floats2bfloat162_rn(ra, rb);
    hi = *reinterpret_cast<uint32_t*>(&H);
    lo = *reinterpret_cast<uint32_t*>(&L);
}

__global__ __launch_bounds__(256, 1)
void rbf_attn_hmma(const float* __restrict__ gq,
                   const float* __restrict__ gk,
                   const float* __restrict__ gv,
                   float* __restrict__ gout) {
    extern __shared__ char smc[];
    const uint32_t smb = smem_u32(smc);
    const int tid  = threadIdx.x;
    const int warp = tid >> 5;
    const int lane = tid & 31;
    const int g    = lane >> 2;     // group 0..7
    const int tig  = lane & 3;      // thread-in-group
    const int iq   = (int)gridDim.x - 1 - (int)blockIdx.x;   // big tiles first
    const int bh   = blockIdx.y;

    const float* qb = gq + (size_t)bh * NSEQ * DDIM;
    const float* kb = gk + (size_t)bh * NSEQ * DDIM;
    const float* vb = gv + (size_t)bh * NSEQ * DDIM;
    float*       ob = gout + (size_t)bh * NSEQ * DDIM;
    float* ksq = (float*)(smc + OFF_KSQ);

    // ---------- prologue: Q -> register A-fragments (hi+lo) + row norms ----------
    const int rowA = warp * 16 + g;       // local q row of a0/a1/a4/a5
    const int rAg  = iq * BM + rowA;      // global
    const int rBg  = rAg + 8;
    uint32_t Qh[8][4], Ql[8][4];
    float q2a = 0.f, q2b = 0.f;
    {
        const float* qA = qb + (size_t)rAg * DDIM;
        const float* qB = qA + 8 * DDIM;
        #pragma unroll
        for (int kb8 = 0; kb8 < 8; kb8++) {
            int c0 = kb8 * 16 + 2 * tig;
            float2 xA0 = *(const float2*)(qA + c0);
            float2 xB0 = *(const float2*)(qB + c0);
            float2 xA1 = *(const float2*)(qA + c0 + 8);
            float2 xB1 = *(const float2*)(qB + c0 + 8);
            q2a += xA0.x*xA0.x + xA0.y*xA0.y + xA1.x*xA1.x + xA1.y*xA1.y;
            q2b += xB0.x*xB0.x + xB0.y*xB0.y + xB1.x*xB1.x + xB1.y*xB1.y;
            split2(xA0.x, xA0.y, Qh[kb8][0], Ql[kb8][0]);
            split2(xB0.x, xB0.y, Qh[kb8][1], Ql[kb8][1]);
            split2(xA1.x, xA1.y, Qh[kb8][2], Ql[kb8][2]);
            split2(xB1.x, xB1.y, Qh[kb8][3], Ql[kb8][3]);
        }
        q2a += __shfl_xor_sync(0xffffffffu, q2a, 1);
        q2a += __shfl_xor_sync(0xffffffffu, q2a, 2);
        q2b += __shfl_xor_sync(0xffffffffu, q2b, 1);
        q2b += __shfl_xor_sync(0xffffffffu, q2b, 2);
        q2a *= SM_SCALE; q2b *= SM_SCALE;
    }

    float O[16][4];
    #pragma unroll
    for (int i = 0; i < 16; i++)
        #pragma unroll
        for (int j = 0; j < 4; j++) O[i][j] = 0.f;

    // per-lane ldmatrix offsets
    // K (non-trans): nrow = (lane&7) + ((lane&16)>>1), kcol bytes += (lane&8)*2
    const uint32_t k_laneoff = (uint32_t)(((lane & 7) + ((lane & 16) >> 1)) * PITCH
                                          + (lane & 8) * 2);
    // V (trans): jrow = (lane&7) + (lane&8), dcol bytes += (lane&16)
    const uint32_t v_laneoff = (uint32_t)(((lane & 7) + (lane & 8)) * PITCH
                                          + (lane & 16));

    const int njt = 2 * iq + 2;
    const int crow = warp;   // convert row: row = u*8 + warp, uniform per warp

    for (int jt = 0; jt < njt; jt++) {
        __syncthreads();   // all warps done reading previous K/V tiles

        // ---- convert K tile (+ksq) and V tile to split-bf16 smem ----
        {
            const float* sk = kb + (size_t)jt * BN * DDIM;
            const float* sv = vb + (size_t)jt * BN * DDIM;
            #pragma unroll
            for (int u = 0; u < 8; u++) {
                int row = u * 8 + crow;
                float4 x = *(const float4*)(sk + (size_t)row * DDIM + lane * 4);
                float s2 = x.x*x.x + x.y*x.y + x.z*x.z + x.w*x.w;
                #pragma unroll
                for (int o = 16; o; o >>= 1) s2 += __shfl_xor_sync(0xffffffffu, s2, o);
                if (lane == 0) ksq[row] = SM_SCALE * s2;
                uint32_t h0, l0, h1, l1;
                split2(x.x, x.y, h0, l0);
                split2(x.z, x.w, h1, l1);
                uint32_t off = (uint32_t)(row * PITCH + lane * 8);
                *(uint2*)(smc + OFF_KHI + off) = make_uint2(h0, h1);
                *(uint2*)(smc + OFF_KLO + off) = make_uint2(l0, l1);

                float4 y = *(const float4*)(sv + (size_t)row * DDIM + lane * 4);
                split2(y.x, y.y, h0, l0);
                split2(y.z, y.w, h1, l1);
                *(uint2*)(smc + OFF_VHI + off) = make_uint2(h0, h1);
                *(uint2*)(smc + OFF_VLO + off) = make_uint2(l0, l1);
            }
        }
        __syncthreads();

        // ---- S = Q K^T : 3-way split bf16 MMAs ----
        float S[8][4];
        #pragma unroll
        for (int i = 0; i < 8; i++)
            #pragma unroll
            for (int j = 0; j < 4; j++) S[i][j] = 0.f;

        #pragma unroll
        for (int kb8 = 0; kb8 < 8; kb8++) {
            #pragma unroll
            for (int ntp = 0; ntp < 4; ntp++) {
                uint32_t a = smb + OFF_KHI + (uint32_t)(ntp * 16 * PITCH + kb8 * 32)
                             + k_laneoff;
                uint32_t bhp[4], blp[4];
                ldsm_x4(bhp, a);
                ldsm_x4(blp, a + (OFF_KLO - OFF_KHI));
                mma_bf16(S[2*ntp],   Qh[kb8], bhp[0], bhp[1]);
                mma_bf16(S[2*ntp+1], Qh[kb8], bhp[2], bhp[3]);
                mma_bf16(S[2*ntp],   Qh[kb8], blp[0], blp[1]);
                mma_bf16(S[2*ntp+1], Qh[kb8], blp[2], blp[3]);
                mma_bf16(S[2*ntp],   Ql[kb8], bhp[0], bhp[1]);
                mma_bf16(S[2*ntp+1], Ql[kb8], bhp[2], bhp[3]);
            }
        }

        // ---- logits -> exp -> causal mask -> P A-fragments (in regs) ----
        uint32_t Ph[4][4], Pl[4][4];
        const bool diag = (jt >= 2 * iq);
        #pragma unroll
        for (int nt = 0; nt < 8; nt++) {
            int n0  = nt * 8 + 2 * tig;
            float ks0 = ksq[n0], ks1 = ksq[n0 + 1];
            int cg = jt * BN + n0;
            float p0 = __expf(fmaf(2.f * SM_SCALE, S[nt][0], -(q2a + ks0)));
            float p1 = __expf(fmaf(2.f * SM_SCALE, S[nt][1], -(q2a + ks1)));
            float p2 = __expf(fmaf(2.f * SM_SCALE, S[nt][2], -(q2b + ks0)));
            float p3 = __expf(fmaf(2.f * SM_SCALE, S[nt][3], -(q2b + ks1)));
            if (diag) {
                if (cg     > rAg) p0 = 0.f;
                if (cg + 1 > rAg) p1 = 0.f;
                if (cg     > rBg) p2 = 0.f;
                if (cg + 1 > rBg) p3 = 0.f;
            }
            int kj = nt >> 1, h = (nt & 1) * 2;
            split2(p0, p1, Ph[kj][h],     Pl[kj][h]);
            split2(p2, p3, Ph[kj][h + 1], Pl[kj][h + 1]);
        }

        // ---- O += P V : 3-way split bf16 MMAs ----
        #pragma unroll
        for (int kj = 0; kj < 4; kj++) {
            #pragma unroll
            for (int dtp = 0; dtp < 8; dtp++) {
                uint32_t a = smb + OFF_VHI + (uint32_t)(kj * 16 * PITCH + dtp * 32)
                             + v_laneoff;
                uint32_t vhp[4], vlp[4];
                ldsm_x4_t(vhp, a);
                ldsm_x4_t(vlp, a + (OFF_VLO - OFF_VHI));
                mma_bf16(O[2*dtp],   Ph[kj], vhp[0], vhp[1]);
                mma_bf16(O[2*dtp+1], Ph[kj], vhp[2], vhp[3]);
                mma_bf16(O[2*dtp],   Ph[kj], vlp[0], vlp[1]);
                mma_bf16(O[2*dtp+1], Ph[kj], vlp[2], vlp[3]);
                mma_bf16(O[2*dtp],   Pl[kj], vhp[0], vhp[1]);
                mma_bf16(O[2*dtp+1], Pl[kj], vhp[2], vhp[3]);
            }
        }
    }

    // ---------- epilogue: O -> gmem ----------
    {
        float* oA = ob + (size_t)rAg * DDIM;
        float* oB = ob + (size_t)rBg * DDIM;
        #pragma unroll
        for (int dt = 0; dt < 16; dt++) {
            int c = dt * 8 + 2 * tig;
            *(float2*)(oA + c) = make_float2(O[dt][0], O[dt][1]);
            *(float2*)(oB + c) = make_float2(O[dt][2], O[dt][3]);
        }
    }
}

extern "C" void kernel_launch(void* const* d_in, const int* in_sizes, int n_in,
                              void* d_out, int out_size) {
    const float* q = (const float*)d_in[0];
    const float* k = (const float*)d_in[1];
    const float* v = (const float*)d_in[2];
    float* out = (float*)d_out;

    cudaFuncSetAttribute(rbf_attn_hmma,
                         cudaFuncAttributeMaxDynamicSharedMemorySize, SMEM_BYTES);
    dim3 grid(NSEQ / BM, 32);   // 16 q-tiles x 32 (b,h)
    rbf_attn_hmma<<<grid, 256, SMEM_BYTES>>>(q, k, v, out);
}

// round 4
// speedup vs baseline: 3.6342x; 1.0713x over previous
#include <cuda_runtime.h>
#include <cuda_bf16.h>
#include <cstdint>

// =====================================================================
// RBF-kernel causal attention, split-bf16 HMMA (sm_103-safe PTX).
// Round 4: pre-pass converts Q/K/V -> hi/lo bf16 global arrays (+row norms)
// ONCE; main kernel streams bf16 tiles with cp.async double buffering so the
// mainloop is ldmatrix + mma + exp only.
//   logit = 2s*(q.k) - s||q||^2 - s||k||^2 ; p = exp(logit), causal ; O = P V
//   Every GEMM = 3 bf16 MMAs (hi*hi + hi*lo + lo*hi) -> ~fp32 precision.
// =====================================================================

namespace {
constexpr int NSEQ = 2048;
constexpr int DDIM = 128;
constexpr int BM   = 128;
constexpr int BN   = 64;
constexpr int NBH  = 32;                     // B*H
constexpr int NROWS = NBH * NSEQ;            // 65536
constexpr size_t TOTE = (size_t)NROWS * DDIM; // 8388608
constexpr float SM_SCALE = 0.08838834764831845f;   // 1/sqrt(128)

constexpr int PITCH = 272;   // smem tile row pitch (bytes)
constexpr uint32_t OFF_KH  = 0;
constexpr uint32_t OFF_KL  = OFF_KH + 64 * PITCH;    // 17408
constexpr uint32_t OFF_VH  = OFF_KL + 64 * PITCH;
constexpr uint32_t OFF_VL  = OFF_VH + 64 * PITCH;
constexpr uint32_t OFF_KSQ = OFF_VL + 64 * PITCH;    // 2 x 256B (double buffered)
constexpr uint32_t SMEM_BYTES = OFF_KSQ + 512 + 128; // ~70.3 KB
}

// ---- persistent scratch (alloc-free workaround) ----
__device__ __nv_bfloat16 g_qhi[TOTE], g_qlo[TOTE];
__device__ __nv_bfloat16 g_khi[TOTE], g_klo[TOTE];
__device__ __nv_bfloat16 g_vhi[TOTE], g_vlo[TOTE];
__device__ float g_qsq[NROWS], g_ksq[NROWS];

__device__ __forceinline__ uint32_t smem_u32(const void* p) {
    uint32_t a;
    asm("{ .reg .u64 t; cvta.to.shared.u64 t, %1; cvt.u32.u64 %0, t; }"
        : "=r"(a) : "l"(p));
    return a;
}
__device__ __forceinline__ void cp16(uint32_t smem_dst, const void* gsrc) {
    asm volatile("cp.async.cg.shared.global [%0], [%1], 16;"
                 :: "r"(smem_dst), "l"(gsrc));
}
__device__ __forceinline__ void cp_commit() {
    asm volatile("cp.async.commit_group;" ::: "memory");
}
__device__ __forceinline__ void cp_wait1() {
    asm volatile("cp.async.wait_group 1;" ::: "memory");
}
__device__ __forceinline__ void ldsm_x4(uint32_t* r, uint32_t addr) {
    asm volatile("ldmatrix.sync.aligned.m8n8.x4.shared.b16 {%0,%1,%2,%3}, [%4];"
                 : "=r"(r[0]), "=r"(r[1]), "=r"(r[2]), "=r"(r[3]) : "r"(addr));
}
__device__ __forceinline__ void ldsm_x4_t(uint32_t* r, uint32_t addr) {
    asm volatile("ldmatrix.sync.aligned.m8n8.x4.trans.shared.b16 {%0,%1,%2,%3}, [%4];"
                 : "=r"(r[0]), "=r"(r[1]), "=r"(r[2]), "=r"(r[3]) : "r"(addr));
}
__device__ __forceinline__ void mma_bf16(float* d, const uint32_t* a,
                                         uint32_t b0, uint32_t b1) {
    asm volatile(
        "mma.sync.aligned.m16n8k16.row.col.f32.bf16.bf16.f32 "
        "{%0,%1,%2,%3}, {%4,%5,%6,%7}, {%8,%9}, {%0,%1,%2,%3};"
        : "+f"(d[0]), "+f"(d[1]), "+f"(d[2]), "+f"(d[3])
        : "r"(a[0]), "r"(a[1]), "r"(a[2]), "r"(a[3]), "r"(b0), "r"(b1));
}
__device__ __forceinline__ void split2(float a, float b, uint32_t& hi, uint32_t& lo) {
    __nv_bfloat162 H = __floats2bfloat162_rn(a, b);
    float ra = a - __bfloat162float(H.x);
    float rb = b - __bfloat162float(H.y);
    __nv_bfloat162 L = __floats2bfloat162_rn(ra, rb);
    hi = *reinterpret_cast<uint32_t*>(&H);
    lo = *reinterpret_cast<uint32_t*>(&L);
}

// =========================== pre-pass ===========================
// One warp per row (same row index for Q, K, V): split to hi/lo bf16,
// write row norms for Q and K.
__global__ __launch_bounds__(256)
void prepass(const float* __restrict__ gq,
             const float* __restrict__ gk,
             const float* __restrict__ gv) {
    const int warp = threadIdx.x >> 5;
    const int lane = threadIdx.x & 31;
    const int row  = blockIdx.x * 8 + warp;
    const size_t e = (size_t)row * DDIM + lane * 4;

    uint32_t h0, l0, h1, l1;

    float4 qx = *(const float4*)(gq + e);
    split2(qx.x, qx.y, h0, l0);
    split2(qx.z, qx.w, h1, l1);
    *(uint2*)&g_qhi[e] = make_uint2(h0, h1);
    *(uint2*)&g_qlo[e] = make_uint2(l0, l1);
    float s2 = qx.x*qx.x + qx.y*qx.y + qx.z*qx.z + qx.w*qx.w;
    #pragma unroll
    for (int o = 16; o; o >>= 1) s2 += __shfl_xor_sync(0xffffffffu, s2, o);
    if (lane == 0) g_qsq[row] = SM_SCALE * s2;

    float4 kx = *(const float4*)(gk + e);
    split2(kx.x, kx.y, h0, l0);
    split2(kx.z, kx.w, h1, l1);
    *(uint2*)&g_khi[e] = make_uint2(h0, h1);
    *(uint2*)&g_klo[e] = make_uint2(l0, l1);
    s2 = kx.x*kx.x + kx.y*kx.y + kx.z*kx.z + kx.w*kx.w;
    #pragma unroll
    for (int o = 16; o; o >>= 1) s2 += __shfl_xor_sync(0xffffffffu, s2, o);
    if (lane == 0) g_ksq[row] = SM_SCALE * s2;

    float4 vx = *(const float4*)(gv + e);
    split2(vx.x, vx.y, h0, l0);
    split2(vx.z, vx.w, h1, l1);
    *(uint2*)&g_vhi[e] = make_uint2(h0, h1);
    *(uint2*)&g_vlo[e] = make_uint2(l0, l1);
}

// =========================== main kernel ===========================
__global__ __launch_bounds__(256, 1)
void rbf_attn_hmma(float* __restrict__ gout) {
    extern __shared__ char smc[];
    const uint32_t smb = smem_u32(smc);
    const int tid  = threadIdx.x;
    const int warp = tid >> 5;
    const int lane = tid & 31;
    const int g    = lane >> 2;
    const int tig  = lane & 3;
    const int iq   = (int)gridDim.x - 1 - (int)blockIdx.x;   // big tiles first
    const int bh   = blockIdx.y;

    const size_t rowbase = (size_t)bh * NSEQ;   // absolute row base for this head
    const int njt = 2 * iq + 2;

    // ---- tile loaders (cp.async): 2048 chunks K(hi+lo), 2048 V, 16 ksq ----
    auto issue_K = [&](int jt) {
        const size_t eb = (rowbase + (size_t)jt * BN) * DDIM;
        #pragma unroll
        for (int i = 0; i < 4; i++) {
            int c = i * 256 + tid;           // 0..1023
            int r = c >> 4, col = c & 15;
            uint32_t d = (uint32_t)(r * PITCH + col * 16);
            cp16(smb + OFF_KH + d, g_khi + eb + r * DDIM + col * 8);
            cp16(smb + OFF_KL + d, g_klo + eb + r * DDIM + col * 8);
        }
        if (tid < 16)
            cp16(smb + OFF_KSQ + (uint32_t)((jt & 1) * 256 + tid * 16),
                 g_ksq + rowbase + jt * BN + tid * 4);
        cp_commit();
    };
    auto issue_V = [&](int jt) {
        const size_t eb = (rowbase + (size_t)jt * BN) * DDIM;
        #pragma unroll
        for (int i = 0; i < 4; i++) {
            int c = i * 256 + tid;
            int r = c >> 4, col = c & 15;
            uint32_t d = (uint32_t)(r * PITCH + col * 16);
            cp16(smb + OFF_VH + d, g_vhi + eb + r * DDIM + col * 8);
            cp16(smb + OFF_VL + d, g_vlo + eb + r * DDIM + col * 8);
        }
        cp_commit();
    };

    issue_K(0);
    issue_V(0);

    // ---- Q fragments straight from global split arrays ----
    const int rowA  = warp * 16 + g;
    const int rA    = iq * BM + rowA;         // row within head
    const int rB    = rA + 8;
    const size_t eA = (rowbase + rA) * (size_t)DDIM;
    const size_t eB = (rowbase + rB) * (size_t)DDIM;
    uint32_t Qh[8][4], Ql[8][4];
    #pragma unroll
    for (int kb8 = 0; kb8 < 8; kb8++) {
        int c0 = kb8 * 16 + 2 * tig;
        Qh[kb8][0] = *(const uint32_t*)&g_qhi[eA + c0];
        Qh[kb8][1] = *(const uint32_t*)&g_qhi[eB + c0];
        Qh[kb8][2] = *(const uint32_t*)&g_qhi[eA + c0 + 8];
        Qh[kb8][3] = *(const uint32_t*)&g_qhi[eB + c0 + 8];
        Ql[kb8][0] = *(const uint32_t*)&g_qlo[eA + c0];
        Ql[kb8][1] = *(const uint32_t*)&g_qlo[eB + c0];
        Ql[kb8][2] = *(const uint32_t*)&g_qlo[eA + c0 + 8];
        Ql[kb8][3] = *(const uint32_t*)&g_qlo[eB + c0 + 8];
    }
    const float q2a = g_qsq[rowbase + rA];
    const float q2b = g_qsq[rowbase + rB];

    float O[16][4];
    #pragma unroll
    for (int i = 0; i < 16; i++)
        #pragma unroll
        for (int j = 0; j < 4; j++) O[i][j] = 0.f;

    const uint32_t k_laneoff = (uint32_t)(((lane & 7) + ((lane & 16) >> 1)) * PITCH
                                          + (lane & 8) * 2);
    const uint32_t v_laneoff = (uint32_t)(((lane & 7) + (lane & 8)) * PITCH
                                          + (lane & 16));
    const float* sksq0 = (const float*)(smc + OFF_KSQ);

    for (int jt = 0; jt < njt; jt++) {
        cp_wait1();          // K(jt) + ksq(jt) arrived (V(jt) may be in flight)
        __syncthreads();

        // ---- S = Q K^T : 3-way split bf16 MMAs ----
        float S[8][4];
        #pragma unroll
        for (int i = 0; i < 8; i++)
            #pragma unroll
            for (int j = 0; j < 4; j++) S[i][j] = 0.f;

        #pragma unroll
        for (int kb8 = 0; kb8 < 8; kb8++) {
            #pragma unroll
            for (int ntp = 0; ntp < 4; ntp++) {
                uint32_t a = smb + OFF_KH + (uint32_t)(ntp * 16 * PITCH + kb8 * 32)
                             + k_laneoff;
                uint32_t bhp[4], blp[4];
                ldsm_x4(bhp, a);
                ldsm_x4(blp, a + (OFF_KL - OFF_KH));
                mma_bf16(S[2*ntp],   Qh[kb8], bhp[0], bhp[1]);
                mma_bf16(S[2*ntp+1], Qh[kb8], bhp[2], bhp[3]);
                mma_bf16(S[2*ntp],   Qh[kb8], blp[0], blp[1]);
                mma_bf16(S[2*ntp+1], Qh[kb8], blp[2], blp[3]);
                mma_bf16(S[2*ntp],   Ql[kb8], bhp[0], bhp[1]);
                mma_bf16(S[2*ntp+1], Ql[kb8], bhp[2], bhp[3]);
            }
        }

        // ---- logits -> exp -> causal mask -> P A-fragments (regs) ----
        uint32_t Ph[4][4], Pl[4][4];
        const bool diag = (jt >= 2 * iq);
        const float* sksq = sksq0 + (jt & 1) * 64;
        #pragma unroll
        for (int nt = 0; nt < 8; nt++) {
            int n0  = nt * 8 + 2 * tig;
            float ks0 = sksq[n0], ks1 = sksq[n0 + 1];
            int cg = jt * BN + n0;
            float p0 = __expf(fmaf(2.f * SM_SCALE, S[nt][0], -(q2a + ks0)));
            float p1 = __expf(fmaf(2.f * SM_SCALE, S[nt][1], -(q2a + ks1)));
            float p2 = __expf(fmaf(2.f * SM_SCALE, S[nt][2], -(q2b + ks0)));
            float p3 = __expf(fmaf(2.f * SM_SCALE, S[nt][3], -(q2b + ks1)));
            if (diag) {
                if (cg     > rA) p0 = 0.f;
                if (cg + 1 > rA) p1 = 0.f;
                if (cg     > rB) p2 = 0.f;
                if (cg + 1 > rB) p3 = 0.f;
            }
            int kj = nt >> 1, h = (nt & 1) * 2;
            split2(p0, p1, Ph[kj][h],     Pl[kj][h]);
            split2(p2, p3, Ph[kj][h + 1], Pl[kj][h + 1]);
        }

        __syncthreads();                 // all warps done with K buffer + ksq
        if (jt + 1 < njt) issue_K(jt + 1);
        cp_wait1();                      // V(jt) arrived (K(jt+1) in flight)
        __syncthreads();

        // ---- O += P V : 3-way split bf16 MMAs ----
        #pragma unroll
        for (int kj = 0; kj < 4; kj++) {
            #pragma unroll
            for (int dtp = 0; dtp < 8; dtp++) {
                uint32_t a = smb + OFF_VH + (uint32_t)(kj * 16 * PITCH + dtp * 32)
                             + v_laneoff;
                uint32_t vhp[4], vlp[4];
                ldsm_x4_t(vhp, a);
                ldsm_x4_t(vlp, a + (OFF_VL - OFF_VH));
                mma_bf16(O[2*dtp],   Ph[kj], vhp[0], vhp[1]);
                mma_bf16(O[2*dtp+1], Ph[kj], vhp[2], vhp[3]);
                mma_bf16(O[2*dtp],   Ph[kj], vlp[0], vlp[1]);
                mma_bf16(O[2*dtp+1], Ph[kj], vlp[2], vlp[3]);
                mma_bf16(O[2*dtp],   Pl[kj], vhp[0], vhp[1]);
                mma_bf16(O[2*dtp+1], Pl[kj], vhp[2], vhp[3]);
            }
        }

        __syncthreads();                 // all warps done with V buffer
        if (jt + 1 < njt) issue_V(jt + 1);
    }

    // ---- epilogue: O -> gmem ----
    float* ob = gout + (size_t)bh * NSEQ * DDIM;
    float* oA = ob + (size_t)rA * DDIM;
    float* oB = ob + (size_t)rB * DDIM;
    #pragma unroll
    for (int dt = 0; dt < 16; dt++) {
        int c = dt * 8 + 2 * tig;
        *(float2*)(oA + c) = make_float2(O[dt][0], O[dt][1]);
        *(float2*)(oB + c) = make_float2(O[dt][2], O[dt][3]);
    }
}

extern "C" void kernel_launch(void* const* d_in, const int* in_sizes, int n_in,
                              void* d_out, int out_size) {
    const float* q = (const float*)d_in[0];
    const float* k = (const float*)d_in[1];
    const float* v = (const float*)d_in[2];
    float* out = (float*)d_out;

    prepass<<<NROWS / 8, 256>>>(q, k, v);

    cudaFuncSetAttribute(rbf_attn_hmma,
                         cudaFuncAttributeMaxDynamicSharedMemorySize, SMEM_BYTES);
    dim3 grid(NSEQ / BM, NBH);
    rbf_attn_hmma<<<grid, 256, SMEM_BYTES>>>(out);
}

// round 5
// speedup vs baseline: 3.9022x; 1.0738x over previous
#include <cuda_runtime.h>
#include <cuda_bf16.h>
#include <cstdint>

// =====================================================================
// RBF-kernel causal attention, split-bf16 HMMA (sm_103-safe PTX).
// Round 5: BM=64, 128 threads/CTA, 2 CTAs/SM — independent CTAs fill each
// other's exp/sync bubbles on the tensor pipe.
// Pre-pass converts Q/K/V -> hi/lo bf16 global arrays (+row norms) once;
// main kernel streams bf16 tiles with cp.async double buffering.
//   logit = 2s*(q.k) - s||q||^2 - s||k||^2 ; p = exp(logit), causal ; O = P V
//   Every GEMM = 3 bf16 MMAs (hi*hi + hi*lo + lo*hi) -> ~fp32 precision.
// =====================================================================

namespace {
constexpr int NSEQ = 2048;
constexpr int DDIM = 128;
constexpr int BM   = 64;
constexpr int BN   = 64;
constexpr int NBH  = 32;                      // B*H
constexpr int NROWS = NBH * NSEQ;             // 65536
constexpr size_t TOTE = (size_t)NROWS * DDIM; // 8388608
constexpr float SM_SCALE = 0.08838834764831845f;   // 1/sqrt(128)

constexpr int PITCH = 272;   // smem tile row pitch (bytes)
constexpr uint32_t OFF_KH  = 0;
constexpr uint32_t OFF_KL  = OFF_KH + 64 * PITCH;    // 17408
constexpr uint32_t OFF_VH  = OFF_KL + 64 * PITCH;
constexpr uint32_t OFF_VL  = OFF_VH + 64 * PITCH;
constexpr uint32_t OFF_KSQ = OFF_VL + 64 * PITCH;    // 2 x 256B (double buffered)
constexpr uint32_t SMEM_BYTES = OFF_KSQ + 512 + 128; // ~70.3 KB per CTA
}

// ---- persistent scratch (alloc-free workaround) ----
__device__ __nv_bfloat16 g_qhi[TOTE], g_qlo[TOTE];
__device__ __nv_bfloat16 g_khi[TOTE], g_klo[TOTE];
__device__ __nv_bfloat16 g_vhi[TOTE], g_vlo[TOTE];
__device__ float g_qsq[NROWS], g_ksq[NROWS];

__device__ __forceinline__ uint32_t smem_u32(const void* p) {
    uint32_t a;
    asm("{ .reg .u64 t; cvta.to.shared.u64 t, %1; cvt.u32.u64 %0, t; }"
        : "=r"(a) : "l"(p));
    return a;
}
__device__ __forceinline__ void cp16(uint32_t smem_dst, const void* gsrc) {
    asm volatile("cp.async.cg.shared.global [%0], [%1], 16;"
                 :: "r"(smem_dst), "l"(gsrc));
}
__device__ __forceinline__ void cp_commit() {
    asm volatile("cp.async.commit_group;" ::: "memory");
}
__device__ __forceinline__ void cp_wait1() {
    asm volatile("cp.async.wait_group 1;" ::: "memory");
}
__device__ __forceinline__ void ldsm_x4(uint32_t* r, uint32_t addr) {
    asm volatile("ldmatrix.sync.aligned.m8n8.x4.shared.b16 {%0,%1,%2,%3}, [%4];"
                 : "=r"(r[0]), "=r"(r[1]), "=r"(r[2]), "=r"(r[3]) : "r"(addr));
}
__device__ __forceinline__ void ldsm_x4_t(uint32_t* r, uint32_t addr) {
    asm volatile("ldmatrix.sync.aligned.m8n8.x4.trans.shared.b16 {%0,%1,%2,%3}, [%4];"
                 : "=r"(r[0]), "=r"(r[1]), "=r"(r[2]), "=r"(r[3]) : "r"(addr));
}
__device__ __forceinline__ void mma_bf16(float* d, const uint32_t* a,
                                         uint32_t b0, uint32_t b1) {
    asm volatile(
        "mma.sync.aligned.m16n8k16.row.col.f32.bf16.bf16.f32 "
        "{%0,%1,%2,%3}, {%4,%5,%6,%7}, {%8,%9}, {%0,%1,%2,%3};"
        : "+f"(d[0]), "+f"(d[1]), "+f"(d[2]), "+f"(d[3])
        : "r"(a[0]), "r"(a[1]), "r"(a[2]), "r"(a[3]), "r"(b0), "r"(b1));
}
__device__ __forceinline__ void split2(float a, float b, uint32_t& hi, uint32_t& lo) {
    __nv_bfloat162 H = __floats2bfloat162_rn(a, b);
    float ra = a - __bfloat162float(H.x);
    float rb = b - __bfloat162float(H.y);
    __nv_bfloat162 L = __floats2bfloat162_rn(ra, rb);
    hi = *reinterpret_cast<uint32_t*>(&H);
    lo = *reinterpret_cast<uint32_t*>(&L);
}

// =========================== pre-pass ===========================
__global__ __launch_bounds__(256)
void prepass(const float* __restrict__ gq,
             const float* __restrict__ gk,
             const float* __restrict__ gv) {
    const int warp = threadIdx.x >> 5;
    const int lane = threadIdx.x & 31;
    const int row  = blockIdx.x * 8 + warp;
    const size_t e = (size_t)row * DDIM + lane * 4;

    uint32_t h0, l0, h1, l1;

    float4 qx = *(const float4*)(gq + e);
    split2(qx.x, qx.y, h0, l0);
    split2(qx.z, qx.w, h1, l1);
    *(uint2*)&g_qhi[e] = make_uint2(h0, h1);
    *(uint2*)&g_qlo[e] = make_uint2(l0, l1);
    float s2 = qx.x*qx.x + qx.y*qx.y + qx.z*qx.z + qx.w*qx.w;
    #pragma unroll
    for (int o = 16; o; o >>= 1) s2 += __shfl_xor_sync(0xffffffffu, s2, o);
    if (lane == 0) g_qsq[row] = SM_SCALE * s2;

    float4 kx = *(const float4*)(gk + e);
    split2(kx.x, kx.y, h0, l0);
    split2(kx.z, kx.w, h1, l1);
    *(uint2*)&g_khi[e] = make_uint2(h0, h1);
    *(uint2*)&g_klo[e] = make_uint2(l0, l1);
    s2 = kx.x*kx.x + kx.y*kx.y + kx.z*kx.z + kx.w*kx.w;
    #pragma unroll
    for (int o = 16; o; o >>= 1) s2 += __shfl_xor_sync(0xffffffffu, s2, o);
    if (lane == 0) g_ksq[row] = SM_SCALE * s2;

    float4 vx = *(const float4*)(gv + e);
    split2(vx.x, vx.y, h0, l0);
    split2(vx.z, vx.w, h1, l1);
    *(uint2*)&g_vhi[e] = make_uint2(h0, h1);
    *(uint2*)&g_vlo[e] = make_uint2(l0, l1);
}

// =========================== main kernel ===========================
__global__ __launch_bounds__(128, 2)
void rbf_attn_hmma(float* __restrict__ gout) {
    extern __shared__ char smc[];
    const uint32_t smb = smem_u32(smc);
    const int tid  = threadIdx.x;
    const int warp = tid >> 5;        // 0..3
    const int lane = tid & 31;
    const int g    = lane >> 2;
    const int tig  = lane & 3;
    const int iq   = (int)gridDim.x - 1 - (int)blockIdx.x;   // big tiles first
    const int bh   = blockIdx.y;

    const size_t rowbase = (size_t)bh * NSEQ;
    const int njt = iq + 1;

    // ---- tile loaders (cp.async): K(hi+lo) 2048 chunks, V 2048, ksq 16 ----
    auto issue_K = [&](int jt) {
        const size_t eb = (rowbase + (size_t)jt * BN) * DDIM;
        #pragma unroll
        for (int i = 0; i < 8; i++) {
            int c = i * 128 + tid;           // 0..1023
            int r = c >> 4, col = c & 15;
            uint32_t d = (uint32_t)(r * PITCH + col * 16);
            cp16(smb + OFF_KH + d, g_khi + eb + r * DDIM + col * 8);
            cp16(smb + OFF_KL + d, g_klo + eb + r * DDIM + col * 8);
        }
        if (tid < 16)
            cp16(smb + OFF_KSQ + (uint32_t)((jt & 1) * 256 + tid * 16),
                 g_ksq + rowbase + jt * BN + tid * 4);
        cp_commit();
    };
    auto issue_V = [&](int jt) {
        const size_t eb = (rowbase + (size_t)jt * BN) * DDIM;
        #pragma unroll
        for (int i = 0; i < 8; i++) {
            int c = i * 128 + tid;
            int r = c >> 4, col = c & 15;
            uint32_t d = (uint32_t)(r * PITCH + col * 16);
            cp16(smb + OFF_VH + d, g_vhi + eb + r * DDIM + col * 8);
            cp16(smb + OFF_VL + d, g_vlo + eb + r * DDIM + col * 8);
        }
        cp_commit();
    };

    issue_K(0);
    issue_V(0);

    // ---- Q fragments straight from global split arrays ----
    const int rowA  = warp * 16 + g;          // 0..63
    const int rA    = iq * BM + rowA;         // row within head
    const int rB    = rA + 8;
    const size_t eA = (rowbase + rA) * (size_t)DDIM;
    const size_t eB = (rowbase + rB) * (size_t)DDIM;
    uint32_t Qh[8][4], Ql[8][4];
    #pragma unroll
    for (int kb8 = 0; kb8 < 8; kb8++) {
        int c0 = kb8 * 16 + 2 * tig;
        Qh[kb8][0] = *(const uint32_t*)&g_qhi[eA + c0];
        Qh[kb8][1] = *(const uint32_t*)&g_qhi[eB + c0];
        Qh[kb8][2] = *(const uint32_t*)&g_qhi[eA + c0 + 8];
        Qh[kb8][3] = *(const uint32_t*)&g_qhi[eB + c0 + 8];
        Ql[kb8][0] = *(const uint32_t*)&g_qlo[eA + c0];
        Ql[kb8][1] = *(const uint32_t*)&g_qlo[eB + c0];
        Ql[kb8][2] = *(const uint32_t*)&g_qlo[eA + c0 + 8];
        Ql[kb8][3] = *(const uint32_t*)&g_qlo[eB + c0 + 8];
    }
    const float q2a = g_qsq[rowbase + rA];
    const float q2b = g_qsq[rowbase + rB];

    float O[16][4];
    #pragma unroll
    for (int i = 0; i < 16; i++)
        #pragma unroll
        for (int j = 0; j < 4; j++) O[i][j] = 0.f;

    const uint32_t k_laneoff = (uint32_t)(((lane & 7) + ((lane & 16) >> 1)) * PITCH
                                          + (lane & 8) * 2);
    const uint32_t v_laneoff = (uint32_t)(((lane & 7) + (lane & 8)) * PITCH
                                          + (lane & 16));
    const float* sksq0 = (const float*)(smc + OFF_KSQ);

    for (int jt = 0; jt < njt; jt++) {
        cp_wait1();          // K(jt) + ksq(jt) arrived (V(jt) may be in flight)
        __syncthreads();

        // ---- S = Q K^T : 3-way split bf16 MMAs ----
        float S[8][4];
        #pragma unroll
        for (int i = 0; i < 8; i++)
            #pragma unroll
            for (int j = 0; j < 4; j++) S[i][j] = 0.f;

        #pragma unroll
        for (int kb8 = 0; kb8 < 8; kb8++) {
            #pragma unroll
            for (int ntp = 0; ntp < 4; ntp++) {
                uint32_t a = smb + OFF_KH + (uint32_t)(ntp * 16 * PITCH + kb8 * 32)
                             + k_laneoff;
                uint32_t bhp[4], blp[4];
                ldsm_x4(bhp, a);
                ldsm_x4(blp, a + (OFF_KL - OFF_KH));
                mma_bf16(S[2*ntp],   Qh[kb8], bhp[0], bhp[1]);
                mma_bf16(S[2*ntp+1], Qh[kb8], bhp[2], bhp[3]);
                mma_bf16(S[2*ntp],   Qh[kb8], blp[0], blp[1]);
                mma_bf16(S[2*ntp+1], Qh[kb8], blp[2], blp[3]);
                mma_bf16(S[2*ntp],   Ql[kb8], bhp[0], bhp[1]);
                mma_bf16(S[2*ntp+1], Ql[kb8], bhp[2], bhp[3]);
            }
        }

        // ---- logits -> exp -> causal mask -> P A-fragments (regs) ----
        uint32_t Ph[4][4], Pl[4][4];
        const bool diag = (jt == iq);
        const float* sksq = sksq0 + (jt & 1) * 64;
        #pragma unroll
        for (int nt = 0; nt < 8; nt++) {
            int n0  = nt * 8 + 2 * tig;
            float ks0 = sksq[n0], ks1 = sksq[n0 + 1];
            int cg = jt * BN + n0;
            float p0 = __expf(fmaf(2.f * SM_SCALE, S[nt][0], -(q2a + ks0)));
            float p1 = __expf(fmaf(2.f * SM_SCALE, S[nt][1], -(q2a + ks1)));
            float p2 = __expf(fmaf(2.f * SM_SCALE, S[nt][2], -(q2b + ks0)));
            float p3 = __expf(fmaf(2.f * SM_SCALE, S[nt][3], -(q2b + ks1)));
            if (diag) {
                if (cg     > rA) p0 = 0.f;
                if (cg + 1 > rA) p1 = 0.f;
                if (cg     > rB) p2 = 0.f;
                if (cg + 1 > rB) p3 = 0.f;
            }
            int kj = nt >> 1, h = (nt & 1) * 2;
            split2(p0, p1, Ph[kj][h],     Pl[kj][h]);
            split2(p2, p3, Ph[kj][h + 1], Pl[kj][h + 1]);
        }

        __syncthreads();                 // all warps done with K buffer + ksq
        if (jt + 1 < njt) issue_K(jt + 1);
        cp_wait1();                      // V(jt) arrived (K(jt+1) in flight)
        __syncthreads();

        // ---- O += P V : 3-way split bf16 MMAs ----
        #pragma unroll
        for (int kj = 0; kj < 4; kj++) {
            #pragma unroll
            for (int dtp = 0; dtp < 8; dtp++) {
                uint32_t a = smb + OFF_VH + (uint32_t)(kj * 16 * PITCH + dtp * 32)
                             + v_laneoff;
                uint32_t vhp[4], vlp[4];
                ldsm_x4_t(vhp, a);
                ldsm_x4_t(vlp, a + (OFF_VL - OFF_VH));
                mma_bf16(O[2*dtp],   Ph[kj], vhp[0], vhp[1]);
                mma_bf16(O[2*dtp+1], Ph[kj], vhp[2], vhp[3]);
                mma_bf16(O[2*dtp],   Ph[kj], vlp[0], vlp[1]);
                mma_bf16(O[2*dtp+1], Ph[kj], vlp[2], vlp[3]);
                mma_bf16(O[2*dtp],   Pl[kj], vhp[0], vhp[1]);
                mma_bf16(O[2*dtp+1], Pl[kj], vhp[2], vhp[3]);
            }
        }

        __syncthreads();                 // all warps done with V buffer
        if (jt + 1 < njt) issue_V(jt + 1);
    }

    // ---- epilogue: O -> gmem ----
    float* ob = gout + (size_t)bh * NSEQ * DDIM;
    float* oA = ob + (size_t)rA * DDIM;
    float* oB = ob + (size_t)rB * DDIM;
    #pragma unroll
    for (int dt = 0; dt < 16; dt++) {
        int c = dt * 8 + 2 * tig;
        *(float2*)(oA + c) = make_float2(O[dt][0], O[dt][1]);
        *(float2*)(oB + c) = make_float2(O[dt][2], O[dt][3]);
    }
}

extern "C" void kernel_launch(void* const* d_in, const int* in_sizes, int n_in,
                              void* d_out, int out_size) {
    const float* q = (const float*)d_in[0];
    const float* k = (const float*)d_in[1];
    const float* v = (const float*)d_in[2];
    float* out = (float*)d_out;

    prepass<<<NROWS / 8, 256>>>(q, k, v);

    cudaFuncSetAttribute(rbf_attn_hmma,
                         cudaFuncAttributeMaxDynamicSharedMemorySize, SMEM_BYTES);
    dim3 grid(NSEQ / BM, NBH);   // 32 q-tiles x 32 (b,h)
    rbf_attn_hmma<<<grid, 128, SMEM_BYTES>>>(out);
}

// round 7
// speedup vs baseline: 5.2005x; 1.3327x over previous
#include <cuda_runtime.h>
#include <cuda_fp16.h>
#include <cuda_bf16.h>
#include <cstdint>

// =====================================================================
// RBF-kernel causal attention, mixed-precision HMMA (sm_103-safe PTX).
// Round 7: QK^T in plain fp16 (1 MMA term; q,k ~ N(0,1) so fp16-safe,
// error ~4e-4), PV in split-bf16 (3 terms; P values ~e^-22 REQUIRE bf16's
// fp32-range exponent — fp16 P underflows, proven in round 6).
//   logit = 2s*(q.k) - s||q||^2 - s||k||^2 ; p = exp(logit), causal ; O = P V
// Norms fp32-exact (prepass). cp.async streaming, 2 CTAs/SM.
// =====================================================================

namespace {
constexpr int NSEQ = 2048;
constexpr int DDIM = 128;
constexpr int BM   = 64;
constexpr int BN   = 64;
constexpr int NBH  = 32;                      // B*H
constexpr int NROWS = NBH * NSEQ;             // 65536
constexpr size_t TOTE = (size_t)NROWS * DDIM; // 8388608
constexpr float SM_SCALE = 0.08838834764831845f;   // 1/sqrt(128)

constexpr int PITCH = 272;   // smem tile row pitch (bytes): 256 data + 16 pad
constexpr uint32_t OFF_K   = 0;                      // K tile fp16
constexpr uint32_t OFF_VH  = OFF_K  + 64 * PITCH;    // V hi (bf16)
constexpr uint32_t OFF_VL  = OFF_VH + 64 * PITCH;    // V lo (bf16)
constexpr uint32_t OFF_KSQ = OFF_VL + 64 * PITCH;    // 2 x 256B (double buffered)
constexpr uint32_t SMEM_BYTES = OFF_KSQ + 512 + 128; // ~53 KB per CTA
}

// ---- persistent scratch (alloc-free workaround) ----
__device__ __half        g_qh[TOTE];
__device__ __half        g_kh[TOTE];
__device__ __nv_bfloat16 g_vhi[TOTE], g_vlo[TOTE];
__device__ float g_qsq[NROWS], g_ksq[NROWS];

__device__ __forceinline__ uint32_t smem_u32(const void* p) {
    uint32_t a;
    asm("{ .reg .u64 t; cvta.to.shared.u64 t, %1; cvt.u32.u64 %0, t; }"
        : "=r"(a) : "l"(p));
    return a;
}
__device__ __forceinline__ void cp16(uint32_t smem_dst, const void* gsrc) {
    asm volatile("cp.async.cg.shared.global [%0], [%1], 16;"
                 :: "r"(smem_dst), "l"(gsrc));
}
__device__ __forceinline__ void cp_commit() {
    asm volatile("cp.async.commit_group;" ::: "memory");
}
__device__ __forceinline__ void cp_wait1() {
    asm volatile("cp.async.wait_group 1;" ::: "memory");
}
__device__ __forceinline__ void ldsm_x4(uint32_t* r, uint32_t addr) {
    asm volatile("ldmatrix.sync.aligned.m8n8.x4.shared.b16 {%0,%1,%2,%3}, [%4];"
                 : "=r"(r[0]), "=r"(r[1]), "=r"(r[2]), "=r"(r[3]) : "r"(addr));
}
__device__ __forceinline__ void ldsm_x4_t(uint32_t* r, uint32_t addr) {
    asm volatile("ldmatrix.sync.aligned.m8n8.x4.trans.shared.b16 {%0,%1,%2,%3}, [%4];"
                 : "=r"(r[0]), "=r"(r[1]), "=r"(r[2]), "=r"(r[3]) : "r"(addr));
}
__device__ __forceinline__ void mma_fp16(float* d, const uint32_t* a,
                                         uint32_t b0, uint32_t b1) {
    asm volatile(
        "mma.sync.aligned.m16n8k16.row.col.f32.f16.f16.f32 "
        "{%0,%1,%2,%3}, {%4,%5,%6,%7}, {%8,%9}, {%0,%1,%2,%3};"
        : "+f"(d[0]), "+f"(d[1]), "+f"(d[2]), "+f"(d[3])
        : "r"(a[0]), "r"(a[1]), "r"(a[2]), "r"(a[3]), "r"(b0), "r"(b1));
}
__device__ __forceinline__ void mma_bf16(float* d, const uint32_t* a,
                                         uint32_t b0, uint32_t b1) {
    asm volatile(
        "mma.sync.aligned.m16n8k16.row.col.f32.bf16.bf16.f32 "
        "{%0,%1,%2,%3}, {%4,%5,%6,%7}, {%8,%9}, {%0,%1,%2,%3};"
        : "+f"(d[0]), "+f"(d[1]), "+f"(d[2]), "+f"(d[3])
        : "r"(a[0]), "r"(a[1]), "r"(a[2]), "r"(a[3]), "r"(b0), "r"(b1));
}
__device__ __forceinline__ void split2_bf(float a, float b, uint32_t& hi, uint32_t& lo) {
    __nv_bfloat162 H = __floats2bfloat162_rn(a, b);
    float ra = a - __bfloat162float(H.x);
    float rb = b - __bfloat162float(H.y);
    __nv_bfloat162 L = __floats2bfloat162_rn(ra, rb);
    hi = *reinterpret_cast<uint32_t*>(&H);
    lo = *reinterpret_cast<uint32_t*>(&L);
}

// =========================== pre-pass ===========================
// One warp per row: Q,K -> fp16; V -> split bf16 (hi+lo); fp32 row norms.
__global__ __launch_bounds__(256)
void prepass(const float* __restrict__ gq,
             const float* __restrict__ gk,
             const float* __restrict__ gv) {
    const int warp = threadIdx.x >> 5;
    const int lane = threadIdx.x & 31;
    const int row  = blockIdx.x * 8 + warp;
    const size_t e = (size_t)row * DDIM + lane * 4;

    float4 qx = *(const float4*)(gq + e);
    {
        __half2 a = __floats2half2_rn(qx.x, qx.y);
        __half2 b = __floats2half2_rn(qx.z, qx.w);
        *(uint2*)&g_qh[e] = make_uint2(*(uint32_t*)&a, *(uint32_t*)&b);
    }
    float s2 = qx.x*qx.x + qx.y*qx.y + qx.z*qx.z + qx.w*qx.w;
    #pragma unroll
    for (int o = 16; o; o >>= 1) s2 += __shfl_xor_sync(0xffffffffu, s2, o);
    if (lane == 0) g_qsq[row] = SM_SCALE * s2;

    float4 kx = *(const float4*)(gk + e);
    {
        __half2 a = __floats2half2_rn(kx.x, kx.y);
        __half2 b = __floats2half2_rn(kx.z, kx.w);
        *(uint2*)&g_kh[e] = make_uint2(*(uint32_t*)&a, *(uint32_t*)&b);
    }
    s2 = kx.x*kx.x + kx.y*kx.y + kx.z*kx.z + kx.w*kx.w;
    #pragma unroll
    for (int o = 16; o; o >>= 1) s2 += __shfl_xor_sync(0xffffffffu, s2, o);
    if (lane == 0) g_ksq[row] = SM_SCALE * s2;

    float4 vx = *(const float4*)(gv + e);
    uint32_t h0, l0, h1, l1;
    split2_bf(vx.x, vx.y, h0, l0);
    split2_bf(vx.z, vx.w, h1, l1);
    *(uint2*)&g_vhi[e] = make_uint2(h0, h1);
    *(uint2*)&g_vlo[e] = make_uint2(l0, l1);
}

// =========================== main kernel ===========================
__global__ __launch_bounds__(128, 2)
void rbf_attn_hmma(float* __restrict__ gout) {
    extern __shared__ char smc[];
    const uint32_t smb = smem_u32(smc);
    const int tid  = threadIdx.x;
    const int warp = tid >> 5;        // 0..3
    const int lane = tid & 31;
    const int g    = lane >> 2;
    const int tig  = lane & 3;
    const int iq   = (int)gridDim.x - 1 - (int)blockIdx.x;   // big tiles first
    const int bh   = blockIdx.y;

    const size_t rowbase = (size_t)bh * NSEQ;
    const int njt = iq + 1;

    // ---- loaders (cp.async). K: 1024 chunks; V hi+lo: 2048; ksq: 16 ----
    auto issue_K = [&](int jt) {
        const size_t eb = (rowbase + (size_t)jt * BN) * DDIM;
        #pragma unroll
        for (int i = 0; i < 8; i++) {
            int c = i * 128 + tid;           // 0..1023
            int r = c >> 4, col = c & 15;
            cp16(smb + OFF_K + (uint32_t)(r * PITCH + col * 16),
                 g_kh + eb + r * DDIM + col * 8);
        }
        if (tid < 16)
            cp16(smb + OFF_KSQ + (uint32_t)((jt & 1) * 256 + tid * 16),
                 g_ksq + rowbase + jt * BN + tid * 4);
        cp_commit();
    };
    auto issue_V = [&](int jt) {
        const size_t eb = (rowbase + (size_t)jt * BN) * DDIM;
        #pragma unroll
        for (int i = 0; i < 8; i++) {
            int c = i * 128 + tid;
            int r = c >> 4, col = c & 15;
            uint32_t d = (uint32_t)(r * PITCH + col * 16);
            const size_t gsrc = eb + r * DDIM + col * 8;
            cp16(smb + OFF_VH + d, g_vhi + gsrc);
            cp16(smb + OFF_VL + d, g_vlo + gsrc);
        }
        cp_commit();
    };

    issue_K(0);
    issue_V(0);

    // ---- Q fragments (fp16) straight from global ----
    const int rowA  = warp * 16 + g;          // 0..63
    const int rA    = iq * BM + rowA;         // row within head
    const int rB    = rA + 8;
    const size_t eA = (rowbase + rA) * (size_t)DDIM;
    const size_t eB = (rowbase + rB) * (size_t)DDIM;
    uint32_t Qf[8][4];
    #pragma unroll
    for (int kb8 = 0; kb8 < 8; kb8++) {
        int c0 = kb8 * 16 + 2 * tig;
        Qf[kb8][0] = *(const uint32_t*)&g_qh[eA + c0];
        Qf[kb8][1] = *(const uint32_t*)&g_qh[eB + c0];
        Qf[kb8][2] = *(const uint32_t*)&g_qh[eA + c0 + 8];
        Qf[kb8][3] = *(const uint32_t*)&g_qh[eB + c0 + 8];
    }
    const float q2a = g_qsq[rowbase + rA];
    const float q2b = g_qsq[rowbase + rB];

    float O[16][4];
    #pragma unroll
    for (int i = 0; i < 16; i++)
        #pragma unroll
        for (int j = 0; j < 4; j++) O[i][j] = 0.f;

    const uint32_t k_laneoff = (uint32_t)(((lane & 7) + ((lane & 16) >> 1)) * PITCH
                                          + (lane & 8) * 2);
    const uint32_t v_laneoff = (uint32_t)(((lane & 7) + (lane & 8)) * PITCH
                                          + (lane & 16));
    const float* sksq0 = (const float*)(smc + OFF_KSQ);

    for (int jt = 0; jt < njt; jt++) {
        cp_wait1();          // K(jt) + ksq(jt) arrived (V(jt) may be in flight)
        __syncthreads();

        // ---- S = Q K^T : single fp16 term ----
        float S[8][4];
        #pragma unroll
        for (int i = 0; i < 8; i++)
            #pragma unroll
            for (int j = 0; j < 4; j++) S[i][j] = 0.f;

        #pragma unroll
        for (int kb8 = 0; kb8 < 8; kb8++) {
            #pragma unroll
            for (int ntp = 0; ntp < 4; ntp++) {
                uint32_t a = smb + OFF_K + (uint32_t)(ntp * 16 * PITCH + kb8 * 32)
                             + k_laneoff;
                uint32_t bp[4];
                ldsm_x4(bp, a);
                mma_fp16(S[2*ntp],   Qf[kb8], bp[0], bp[1]);
                mma_fp16(S[2*ntp+1], Qf[kb8], bp[2], bp[3]);
            }
        }

        // ---- logits -> exp -> causal mask -> split-bf16 P A-frags ----
        uint32_t Ph[4][4], Pl[4][4];
        const bool diag = (jt == iq);
        const float* sksq = sksq0 + (jt & 1) * 64;
        #pragma unroll
        for (int nt = 0; nt < 8; nt++) {
            int n0  = nt * 8 + 2 * tig;
            float ks0 = sksq[n0], ks1 = sksq[n0 + 1];
            int cg = jt * BN + n0;
            float p0 = __expf(fmaf(2.f * SM_SCALE, S[nt][0], -(q2a + ks0)));
            float p1 = __expf(fmaf(2.f * SM_SCALE, S[nt][1], -(q2a + ks1)));
            float p2 = __expf(fmaf(2.f * SM_SCALE, S[nt][2], -(q2b + ks0)));
            float p3 = __expf(fmaf(2.f * SM_SCALE, S[nt][3], -(q2b + ks1)));
            if (diag) {
                if (cg     > rA) p0 = 0.f;
                if (cg + 1 > rA) p1 = 0.f;
                if (cg     > rB) p2 = 0.f;
                if (cg + 1 > rB) p3 = 0.f;
            }
            int kj = nt >> 1, h = (nt & 1) * 2;
            split2_bf(p0, p1, Ph[kj][h],     Pl[kj][h]);
            split2_bf(p2, p3, Ph[kj][h + 1], Pl[kj][h + 1]);
        }

        __syncthreads();                 // all warps done with K buffer + ksq
        if (jt + 1 < njt) issue_K(jt + 1);
        cp_wait1();                      // V(jt) arrived (K(jt+1) in flight)
        __syncthreads();

        // ---- O += P V : 3-way split bf16 MMAs ----
        #pragma unroll
        for (int kj = 0; kj < 4; kj++) {
            #pragma unroll
            for (int dtp = 0; dtp < 8; dtp++) {
                uint32_t a = smb + OFF_VH + (uint32_t)(kj * 16 * PITCH + dtp * 32)
                             + v_laneoff;
                uint32_t vhp[4], vlp[4];
                ldsm_x4_t(vhp, a);
                ldsm_x4_t(vlp, a + (OFF_VL - OFF_VH));
                mma_bf16(O[2*dtp],   Ph[kj], vhp[0], vhp[1]);
                mma_bf16(O[2*dtp+1], Ph[kj], vhp[2], vhp[3]);
                mma_bf16(O[2*dtp],   Ph[kj], vlp[0], vlp[1]);
                mma_bf16(O[2*dtp+1], Ph[kj], vlp[2], vlp[3]);
                mma_bf16(O[2*dtp],   Pl[kj], vhp[0], vhp[1]);
                mma_bf16(O[2*dtp+1], Pl[kj], vhp[2], vhp[3]);
            }
        }

        __syncthreads();                 // all warps done with V buffer
        if (jt + 1 < njt) issue_V(jt + 1);
    }

    // ---- epilogue: O -> gmem ----
    float* ob = gout + (size_t)bh * NSEQ * DDIM;
    float* oA = ob + (size_t)rA * DDIM;
    float* oB = ob + (size_t)rB * DDIM;
    #pragma unroll
    for (int dt = 0; dt < 16; dt++) {
        int c = dt * 8 + 2 * tig;
        *(float2*)(oA + c) = make_float2(O[dt][0], O[dt][1]);
        *(float2*)(oB + c) = make_float2(O[dt][2], O[dt][3]);
    }
}

extern "C" void kernel_launch(void* const* d_in, const int* in_sizes, int n_in,
                              void* d_out, int out_size) {
    const float* q = (const float*)d_in[0];
    const float* k = (const float*)d_in[1];
    const float* v = (const float*)d_in[2];
    float* out = (float*)d_out;

    prepass<<<NROWS / 8, 256>>>(q, k, v);

    cudaFuncSetAttribute(rbf_attn_hmma,
                         cudaFuncAttributeMaxDynamicSharedMemorySize, SMEM_BYTES);
    dim3 grid(NSEQ / BM, NBH);   // 32 q-tiles x 32 (b,h)
    rbf_attn_hmma<<<grid, 128, SMEM_BYTES>>>(out);
}

// round 8
// speedup vs baseline: 7.6128x; 1.4639x over previous
#include <cuda_runtime.h>
#include <cuda_fp16.h>
#include <cstdint>

// =====================================================================
// RBF-kernel causal attention, fp16 HMMA with per-row power-of-2 P scaling.
//   l2_ij = log2e*(2s*(q.k) - s||q||^2 - s||k||^2)  (causal mask -> -3e30)
//   p = 2^(l2 - b_row), b_row = running max(l2) - 14  (p fits fp16: <= 2^14,
//   relative row range 2^-28 within fp16 reach). O accumulated at scale 2^-b,
//   rescaled by 2^(b_old-b_new) when b grows; final O *= 2^b.
// QK^T: 1-term fp16 (error ~4.9e-4, calibrated round 7).
// PV:   1-term fp16 on scaled P (error ~1.4e-4). 128 MMAs/warp-tile total.
// cp.async streaming of K,V tiles; 2 CTAs/SM.
// =====================================================================

namespace {
constexpr int NSEQ = 2048;
constexpr int DDIM = 128;
constexpr int BM   = 64;
constexpr int BN   = 64;
constexpr int NBH  = 32;                      // B*H
constexpr int NROWS = NBH * NSEQ;             // 65536
constexpr size_t TOTE = (size_t)NROWS * DDIM; // 8388608
constexpr float SM_SCALE = 0.08838834764831845f;   // 1/sqrt(128)
constexpr float LOG2E    = 1.4426950408889634f;
constexpr float C2       = 2.0f * SM_SCALE * LOG2E;   // logit->log2 fused

constexpr int PITCH = 272;   // smem tile row pitch (bytes): 256 data + 16 pad
constexpr uint32_t OFF_K   = 0;                      // K tile fp16
constexpr uint32_t OFF_V   = OFF_K + 64 * PITCH;     // V tile fp16
constexpr uint32_t OFF_KSQ = OFF_V + 64 * PITCH;     // 2 x 256B (double buffered)
constexpr uint32_t SMEM_BYTES = OFF_KSQ + 512 + 128; // ~35.5 KB per CTA
}

// ---- persistent scratch (alloc-free workaround) ----
__device__ __half g_qh[TOTE];
__device__ __half g_kh[TOTE];
__device__ __half g_vh[TOTE];
__device__ float  g_qsq[NROWS], g_ksq[NROWS];   // log2e * s * ||.||^2

__device__ __forceinline__ uint32_t smem_u32(const void* p) {
    uint32_t a;
    asm("{ .reg .u64 t; cvta.to.shared.u64 t, %1; cvt.u32.u64 %0, t; }"
        : "=r"(a) : "l"(p));
    return a;
}
__device__ __forceinline__ void cp16(uint32_t smem_dst, const void* gsrc) {
    asm volatile("cp.async.cg.shared.global [%0], [%1], 16;"
                 :: "r"(smem_dst), "l"(gsrc));
}
__device__ __forceinline__ void cp_commit() {
    asm volatile("cp.async.commit_group;" ::: "memory");
}
__device__ __forceinline__ void cp_wait1() {
    asm volatile("cp.async.wait_group 1;" ::: "memory");
}
__device__ __forceinline__ void ldsm_x4(uint32_t* r, uint32_t addr) {
    asm volatile("ldmatrix.sync.aligned.m8n8.x4.shared.b16 {%0,%1,%2,%3}, [%4];"
                 : "=r"(r[0]), "=r"(r[1]), "=r"(r[2]), "=r"(r[3]) : "r"(addr));
}
__device__ __forceinline__ void ldsm_x4_t(uint32_t* r, uint32_t addr) {
    asm volatile("ldmatrix.sync.aligned.m8n8.x4.trans.shared.b16 {%0,%1,%2,%3}, [%4];"
                 : "=r"(r[0]), "=r"(r[1]), "=r"(r[2]), "=r"(r[3]) : "r"(addr));
}
__device__ __forceinline__ void mma_fp16(float* d, const uint32_t* a,
                                         uint32_t b0, uint32_t b1) {
    asm volatile(
        "mma.sync.aligned.m16n8k16.row.col.f32.f16.f16.f32 "
        "{%0,%1,%2,%3}, {%4,%5,%6,%7}, {%8,%9}, {%0,%1,%2,%3};"
        : "+f"(d[0]), "+f"(d[1]), "+f"(d[2]), "+f"(d[3])
        : "r"(a[0]), "r"(a[1]), "r"(a[2]), "r"(a[3]), "r"(b0), "r"(b1));
}
__device__ __forceinline__ float ex2(float x) {
    float y;
    asm("ex2.approx.ftz.f32 %0, %1;" : "=f"(y) : "f"(x));
    return y;
}

// =========================== pre-pass ===========================
// One warp per row: Q,K,V -> fp16; log2e-scaled fp32 row norms for Q,K.
__global__ __launch_bounds__(256)
void prepass(const float* __restrict__ gq,
             const float* __restrict__ gk,
             const float* __restrict__ gv) {
    const int warp = threadIdx.x >> 5;
    const int lane = threadIdx.x & 31;
    const int row  = blockIdx.x * 8 + warp;
    const size_t e = (size_t)row * DDIM + lane * 4;

    float4 qx = *(const float4*)(gq + e);
    {
        __half2 a = __floats2half2_rn(qx.x, qx.y);
        __half2 b = __floats2half2_rn(qx.z, qx.w);
        *(uint2*)&g_qh[e] = make_uint2(*(uint32_t*)&a, *(uint32_t*)&b);
    }
    float s2 = qx.x*qx.x + qx.y*qx.y + qx.z*qx.z + qx.w*qx.w;
    #pragma unroll
    for (int o = 16; o; o >>= 1) s2 += __shfl_xor_sync(0xffffffffu, s2, o);
    if (lane == 0) g_qsq[row] = (SM_SCALE * LOG2E) * s2;

    float4 kx = *(const float4*)(gk + e);
    {
        __half2 a = __floats2half2_rn(kx.x, kx.y);
        __half2 b = __floats2half2_rn(kx.z, kx.w);
        *(uint2*)&g_kh[e] = make_uint2(*(uint32_t*)&a, *(uint32_t*)&b);
    }
    s2 = kx.x*kx.x + kx.y*kx.y + kx.z*kx.z + kx.w*kx.w;
    #pragma unroll
    for (int o = 16; o; o >>= 1) s2 += __shfl_xor_sync(0xffffffffu, s2, o);
    if (lane == 0) g_ksq[row] = (SM_SCALE * LOG2E) * s2;

    float4 vx = *(const float4*)(gv + e);
    {
        __half2 a = __floats2half2_rn(vx.x, vx.y);
        __half2 b = __floats2half2_rn(vx.z, vx.w);
        *(uint2*)&g_vh[e] = make_uint2(*(uint32_t*)&a, *(uint32_t*)&b);
    }
}

// =========================== main kernel ===========================
__global__ __launch_bounds__(128, 2)
void rbf_attn_hmma(float* __restrict__ gout) {
    extern __shared__ char smc[];
    const uint32_t smb = smem_u32(smc);
    const int tid  = threadIdx.x;
    const int warp = tid >> 5;        // 0..3
    const int lane = tid & 31;
    const int g    = lane >> 2;
    const int tig  = lane & 3;
    const int iq   = (int)gridDim.x - 1 - (int)blockIdx.x;   // big tiles first
    const int bh   = blockIdx.y;

    const size_t rowbase = (size_t)bh * NSEQ;
    const int njt = iq + 1;

    // ---- loaders (cp.async). K: 1024 chunks + ksq; V: 1024 ----
    auto issue_K = [&](int jt) {
        const size_t eb = (rowbase + (size_t)jt * BN) * DDIM;
        #pragma unroll
        for (int i = 0; i < 8; i++) {
            int c = i * 128 + tid;           // 0..1023
            int r = c >> 4, col = c & 15;
            cp16(smb + OFF_K + (uint32_t)(r * PITCH + col * 16),
                 g_kh + eb + r * DDIM + col * 8);
        }
        if (tid < 16)
            cp16(smb + OFF_KSQ + (uint32_t)((jt & 1) * 256 + tid * 16),
                 g_ksq + rowbase + jt * BN + tid * 4);
        cp_commit();
    };
    auto issue_V = [&](int jt) {
        const size_t eb = (rowbase + (size_t)jt * BN) * DDIM;
        #pragma unroll
        for (int i = 0; i < 8; i++) {
            int c = i * 128 + tid;
            int r = c >> 4, col = c & 15;
            cp16(smb + OFF_V + (uint32_t)(r * PITCH + col * 16),
                 g_vh + eb + r * DDIM + col * 8);
        }
        cp_commit();
    };

    issue_K(0);
    issue_V(0);

    // ---- Q fragments (fp16) straight from global ----
    const int rowA  = warp * 16 + g;          // 0..63
    const int rA    = iq * BM + rowA;         // row within head
    const int rB    = rA + 8;
    const size_t eA = (rowbase + rA) * (size_t)DDIM;
    const size_t eB = (rowbase + rB) * (size_t)DDIM;
    uint32_t Qf[8][4];
    #pragma unroll
    for (int kb8 = 0; kb8 < 8; kb8++) {
        int c0 = kb8 * 16 + 2 * tig;
        Qf[kb8][0] = *(const uint32_t*)&g_qh[eA + c0];
        Qf[kb8][1] = *(const uint32_t*)&g_qh[eB + c0];
        Qf[kb8][2] = *(const uint32_t*)&g_qh[eA + c0 + 8];
        Qf[kb8][3] = *(const uint32_t*)&g_qh[eB + c0 + 8];
    }
    const float q2a = g_qsq[rowbase + rA];
    const float q2b = g_qsq[rowbase + rB];

    float O[16][4];
    #pragma unroll
    for (int i = 0; i < 16; i++)
        #pragma unroll
        for (int j = 0; j < 4; j++) O[i][j] = 0.f;
    float b_a = -3e30f, b_b = -3e30f;   // running log2-bias per row half

    const uint32_t k_laneoff = (uint32_t)(((lane & 7) + ((lane & 16) >> 1)) * PITCH
                                          + (lane & 8) * 2);
    const uint32_t v_laneoff = (uint32_t)(((lane & 7) + (lane & 8)) * PITCH
                                          + (lane & 16));
    const float* sksq0 = (const float*)(smc + OFF_KSQ);

    for (int jt = 0; jt < njt; jt++) {
        cp_wait1();          // K(jt) + ksq(jt) arrived (V(jt) may be in flight)
        __syncthreads();

        // ---- S = Q K^T : single fp16 term ----
        float S[8][4];
        #pragma unroll
        for (int i = 0; i < 8; i++)
            #pragma unroll
            for (int j = 0; j < 4; j++) S[i][j] = 0.f;

        #pragma unroll
        for (int kb8 = 0; kb8 < 8; kb8++) {
            #pragma unroll
            for (int ntp = 0; ntp < 4; ntp++) {
                uint32_t a = smb + OFF_K + (uint32_t)(ntp * 16 * PITCH + kb8 * 32)
                             + k_laneoff;
                uint32_t bp[4];
                ldsm_x4(bp, a);
                mma_fp16(S[2*ntp],   Qf[kb8], bp[0], bp[1]);
                mma_fp16(S[2*ntp+1], Qf[kb8], bp[2], bp[3]);
            }
        }

        // ---- log2-logits + mask + row max ----
        const bool diag = (jt == iq);
        const float* sksq = sksq0 + (jt & 1) * 64;
        float mxa = -3e30f, mxb = -3e30f;
        #pragma unroll
        for (int nt = 0; nt < 8; nt++) {
            int n0  = nt * 8 + 2 * tig;
            float ks0 = sksq[n0], ks1 = sksq[n0 + 1];
            int cg = jt * BN + n0;
            float a0 = fmaf(C2, S[nt][0], -(q2a + ks0));
            float a1 = fmaf(C2, S[nt][1], -(q2a + ks1));
            float c0 = fmaf(C2, S[nt][2], -(q2b + ks0));
            float c1 = fmaf(C2, S[nt][3], -(q2b + ks1));
            if (diag) {
                if (cg     > rA) a0 = -3e30f;
                if (cg + 1 > rA) a1 = -3e30f;
                if (cg     > rB) c0 = -3e30f;
                if (cg + 1 > rB) c1 = -3e30f;
            }
            S[nt][0] = a0; S[nt][1] = a1; S[nt][2] = c0; S[nt][3] = c1;
            mxa = fmaxf(mxa, fmaxf(a0, a1));
            mxb = fmaxf(mxb, fmaxf(c0, c1));
        }
        mxa = fmaxf(mxa, __shfl_xor_sync(0xffffffffu, mxa, 1));
        mxa = fmaxf(mxa, __shfl_xor_sync(0xffffffffu, mxa, 2));
        mxb = fmaxf(mxb, __shfl_xor_sync(0xffffffffu, mxb, 1));
        mxb = fmaxf(mxb, __shfl_xor_sync(0xffffffffu, mxb, 2));

        // ---- update bias, rescale O if it grew ----
        float bna = fmaxf(b_a, mxa - 14.f);
        if (bna > b_a) {
            float f = ex2(b_a - bna);
            #pragma unroll
            for (int dt = 0; dt < 16; dt++) { O[dt][0] *= f; O[dt][1] *= f; }
            b_a = bna;
        }
        float bnb = fmaxf(b_b, mxb - 14.f);
        if (bnb > b_b) {
            float f = ex2(b_b - bnb);
            #pragma unroll
            for (int dt = 0; dt < 16; dt++) { O[dt][2] *= f; O[dt][3] *= f; }
            b_b = bnb;
        }

        // ---- p = 2^(l2 - b) -> fp16 A-fragments ----
        uint32_t Pf[4][4];
        #pragma unroll
        for (int nt = 0; nt < 8; nt++) {
            float p0 = ex2(S[nt][0] - b_a);
            float p1 = ex2(S[nt][1] - b_a);
            float p2 = ex2(S[nt][2] - b_b);
            float p3 = ex2(S[nt][3] - b_b);
            int kj = nt >> 1, h = (nt & 1) * 2;
            __half2 ha = __floats2half2_rn(p0, p1);
            __half2 hb = __floats2half2_rn(p2, p3);
            Pf[kj][h]     = *(uint32_t*)&ha;
            Pf[kj][h + 1] = *(uint32_t*)&hb;
        }

        __syncthreads();                 // all warps done with K buffer + ksq
        if (jt + 1 < njt) issue_K(jt + 1);
        cp_wait1();                      // V(jt) arrived (K(jt+1) in flight)
        __syncthreads();

        // ---- O += P V : single fp16 term ----
        #pragma unroll
        for (int kj = 0; kj < 4; kj++) {
            #pragma unroll
            for (int dtp = 0; dtp < 8; dtp++) {
                uint32_t a = smb + OFF_V + (uint32_t)(kj * 16 * PITCH + dtp * 32)
                             + v_laneoff;
                uint32_t vp[4];
                ldsm_x4_t(vp, a);
                mma_fp16(O[2*dtp],   Pf[kj], vp[0], vp[1]);
                mma_fp16(O[2*dtp+1], Pf[kj], vp[2], vp[3]);
            }
        }

        __syncthreads();                 // all warps done with V buffer
        if (jt + 1 < njt) issue_V(jt + 1);
    }

    // ---- epilogue: descale (O_true = O * 2^b) and store ----
    const float fa = ex2(b_a);
    const float fb = ex2(b_b);
    float* ob = gout + (size_t)bh * NSEQ * DDIM;
    float* oA = ob + (size_t)rA * DDIM;
    float* oB = ob + (size_t)rB * DDIM;
    #pragma unroll
    for (int dt = 0; dt < 16; dt++) {
        int c = dt * 8 + 2 * tig;
        *(float2*)(oA + c) = make_float2(O[dt][0] * fa, O[dt][1] * fa);
        *(float2*)(oB + c) = make_float2(O[dt][2] * fb, O[dt][3] * fb);
    }
}

extern "C" void kernel_launch(void* const* d_in, const int* in_sizes, int n_in,
                              void* d_out, int out_size) {
    const float* q = (const float*)d_in[0];
    const float* k = (const float*)d_in[1];
    const float* v = (const float*)d_in[2];
    float* out = (float*)d_out;

    prepass<<<NROWS / 8, 256>>>(q, k, v);

    cudaFuncSetAttribute(rbf_attn_hmma,
                         cudaFuncAttributeMaxDynamicSharedMemorySize, SMEM_BYTES);
    dim3 grid(NSEQ / BM, NBH);   // 32 q-tiles x 32 (b,h)
    rbf_attn_hmma<<<grid, 128, SMEM_BYTES>>>(out);
}

// round 9
// speedup vs baseline: 8.2817x; 1.0879x over previous
#include <cuda_runtime.h>
#include <cuda_fp16.h>
#include <cstdint>

// =====================================================================
// RBF-kernel causal attention, fp16 HMMA + per-row power-of-2 P scaling.
// Round 9: (a) K+V+ksq in ONE cp.async stage -> 2 barriers/tile (was 4);
// (b) exp fused into PV loop at 16-col chunks so MUFU overlaps tensor pipe.
//   l2_ij = log2e*(2s*(q.k) - s||q||^2 - s||k||^2); p = 2^(l2 - b_row);
//   b_row = running max(l2) - 14; O accumulated at 2^-b, rescaled on growth.
// QK^T and PV both 1-term fp16 (error budget calibrated rounds 7-8: ~5.4e-4).
// =====================================================================

namespace {
constexpr int NSEQ = 2048;
constexpr int DDIM = 128;
constexpr int BM   = 64;
constexpr int BN   = 64;
constexpr int NBH  = 32;                      // B*H
constexpr int NROWS = NBH * NSEQ;             // 65536
constexpr size_t TOTE = (size_t)NROWS * DDIM; // 8388608
constexpr float SM_SCALE = 0.08838834764831845f;   // 1/sqrt(128)
constexpr float LOG2E    = 1.4426950408889634f;
constexpr float C2       = 2.0f * SM_SCALE * LOG2E;

constexpr int PITCH = 272;   // smem tile row pitch (bytes): 256 data + 16 pad
constexpr uint32_t OFF_V       = 64 * PITCH;            // V offset inside stage
constexpr uint32_t STAGE_BYTES = 2u * 64 * PITCH;       // K + V = 34816
constexpr uint32_t OFF_KSQ     = 2 * STAGE_BYTES;       // 2 x 256B
constexpr uint32_t SMEM_BYTES  = OFF_KSQ + 512 + 128;   // 70272 per CTA
}

// ---- persistent scratch (alloc-free workaround) ----
__device__ __half g_qh[TOTE];
__device__ __half g_kh[TOTE];
__device__ __half g_vh[TOTE];
__device__ float  g_qsq[NROWS], g_ksq[NROWS];   // log2e * s * ||.||^2

__device__ __forceinline__ uint32_t smem_u32(const void* p) {
    uint32_t a;
    asm("{ .reg .u64 t; cvta.to.shared.u64 t, %1; cvt.u32.u64 %0, t; }"
        : "=r"(a) : "l"(p));
    return a;
}
__device__ __forceinline__ void cp16(uint32_t smem_dst, const void* gsrc) {
    asm volatile("cp.async.cg.shared.global [%0], [%1], 16;"
                 :: "r"(smem_dst), "l"(gsrc));
}
__device__ __forceinline__ void cp_commit() {
    asm volatile("cp.async.commit_group;" ::: "memory");
}
__device__ __forceinline__ void cp_wait1() {
    asm volatile("cp.async.wait_group 1;" ::: "memory");
}
__device__ __forceinline__ void ldsm_x4(uint32_t* r, uint32_t addr) {
    asm volatile("ldmatrix.sync.aligned.m8n8.x4.shared.b16 {%0,%1,%2,%3}, [%4];"
                 : "=r"(r[0]), "=r"(r[1]), "=r"(r[2]), "=r"(r[3]) : "r"(addr));
}
__device__ __forceinline__ void ldsm_x4_t(uint32_t* r, uint32_t addr) {
    asm volatile("ldmatrix.sync.aligned.m8n8.x4.trans.shared.b16 {%0,%1,%2,%3}, [%4];"
                 : "=r"(r[0]), "=r"(r[1]), "=r"(r[2]), "=r"(r[3]) : "r"(addr));
}
__device__ __forceinline__ void mma_fp16(float* d, const uint32_t* a,
                                         uint32_t b0, uint32_t b1) {
    asm volatile(
        "mma.sync.aligned.m16n8k16.row.col.f32.f16.f16.f32 "
        "{%0,%1,%2,%3}, {%4,%5,%6,%7}, {%8,%9}, {%0,%1,%2,%3};"
        : "+f"(d[0]), "+f"(d[1]), "+f"(d[2]), "+f"(d[3])
        : "r"(a[0]), "r"(a[1]), "r"(a[2]), "r"(a[3]), "r"(b0), "r"(b1));
}
__device__ __forceinline__ float ex2(float x) {
    float y;
    asm("ex2.approx.ftz.f32 %0, %1;" : "=f"(y) : "f"(x));
    return y;
}

// =========================== pre-pass ===========================
__global__ __launch_bounds__(256)
void prepass(const float* __restrict__ gq,
             const float* __restrict__ gk,
             const float* __restrict__ gv) {
    const int warp = threadIdx.x >> 5;
    const int lane = threadIdx.x & 31;
    const int row  = blockIdx.x * 8 + warp;
    const size_t e = (size_t)row * DDIM + lane * 4;

    float4 qx = *(const float4*)(gq + e);
    {
        __half2 a = __floats2half2_rn(qx.x, qx.y);
        __half2 b = __floats2half2_rn(qx.z, qx.w);
        *(uint2*)&g_qh[e] = make_uint2(*(uint32_t*)&a, *(uint32_t*)&b);
    }
    float s2 = qx.x*qx.x + qx.y*qx.y + qx.z*qx.z + qx.w*qx.w;
    #pragma unroll
    for (int o = 16; o; o >>= 1) s2 += __shfl_xor_sync(0xffffffffu, s2, o);
    if (lane == 0) g_qsq[row] = (SM_SCALE * LOG2E) * s2;

    float4 kx = *(const float4*)(gk + e);
    {
        __half2 a = __floats2half2_rn(kx.x, kx.y);
        __half2 b = __floats2half2_rn(kx.z, kx.w);
        *(uint2*)&g_kh[e] = make_uint2(*(uint32_t*)&a, *(uint32_t*)&b);
    }
    s2 = kx.x*kx.x + kx.y*kx.y + kx.z*kx.z + kx.w*kx.w;
    #pragma unroll
    for (int o = 16; o; o >>= 1) s2 += __shfl_xor_sync(0xffffffffu, s2, o);
    if (lane == 0) g_ksq[row] = (SM_SCALE * LOG2E) * s2;

    float4 vx = *(const float4*)(gv + e);
    {
        __half2 a = __floats2half2_rn(vx.x, vx.y);
        __half2 b = __floats2half2_rn(vx.z, vx.w);
        *(uint2*)&g_vh[e] = make_uint2(*(uint32_t*)&a, *(uint32_t*)&b);
    }
}

// =========================== main kernel ===========================
__global__ __launch_bounds__(128, 2)
void rbf_attn_hmma(float* __restrict__ gout) {
    extern __shared__ char smc[];
    const uint32_t smb = smem_u32(smc);
    const int tid  = threadIdx.x;
    const int warp = tid >> 5;        // 0..3
    const int lane = tid & 31;
    const int g    = lane >> 2;
    const int tig  = lane & 3;
    const int iq   = (int)gridDim.x - 1 - (int)blockIdx.x;   // big tiles first
    const int bh   = blockIdx.y;

    const size_t rowbase = (size_t)bh * NSEQ;
    const int njt = iq + 1;

    // ---- stage loader: K + V + ksq of tile jt, one commit group ----
    auto issue_KV = [&](int jt) {
        if (jt < njt) {
            const uint32_t stg = (uint32_t)(jt & 1) * STAGE_BYTES;
            const size_t eb = (rowbase + (size_t)jt * BN) * DDIM;
            #pragma unroll
            for (int i = 0; i < 8; i++) {
                int c = i * 128 + tid;           // 0..1023
                int r = c >> 4, col = c & 15;
                uint32_t d = (uint32_t)(r * PITCH + col * 16);
                const size_t gsrc = eb + r * DDIM + col * 8;
                cp16(smb + stg + d,         g_kh + gsrc);
                cp16(smb + stg + OFF_V + d, g_vh + gsrc);
            }
            if (tid < 16)
                cp16(smb + OFF_KSQ + (uint32_t)((jt & 1) * 256 + tid * 16),
                     g_ksq + rowbase + jt * BN + tid * 4);
        }
        cp_commit();
    };

    issue_KV(0);
    issue_KV(1);

    // ---- Q fragments (fp16) straight from global ----
    const int rowA  = warp * 16 + g;          // 0..63
    const int rA    = iq * BM + rowA;         // row within head
    const int rB    = rA + 8;
    const size_t eA = (rowbase + rA) * (size_t)DDIM;
    const size_t eB = (rowbase + rB) * (size_t)DDIM;
    uint32_t Qf[8][4];
    #pragma unroll
    for (int kb8 = 0; kb8 < 8; kb8++) {
        int c0 = kb8 * 16 + 2 * tig;
        Qf[kb8][0] = *(const uint32_t*)&g_qh[eA + c0];
        Qf[kb8][1] = *(const uint32_t*)&g_qh[eB + c0];
        Qf[kb8][2] = *(const uint32_t*)&g_qh[eA + c0 + 8];
        Qf[kb8][3] = *(const uint32_t*)&g_qh[eB + c0 + 8];
    }
    const float q2a = g_qsq[rowbase + rA];
    const float q2b = g_qsq[rowbase + rB];

    float O[16][4];
    #pragma unroll
    for (int i = 0; i < 16; i++)
        #pragma unroll
        for (int j = 0; j < 4; j++) O[i][j] = 0.f;
    float b_a = -3e30f, b_b = -3e30f;   // running log2-bias per row half

    const uint32_t k_laneoff = (uint32_t)(((lane & 7) + ((lane & 16) >> 1)) * PITCH
                                          + (lane & 8) * 2);
    const uint32_t v_laneoff = (uint32_t)(((lane & 7) + (lane & 8)) * PITCH
                                          + (lane & 16));
    const float* sksq0 = (const float*)(smc + OFF_KSQ);

    for (int jt = 0; jt < njt; jt++) {
        const uint32_t stg = (uint32_t)(jt & 1) * STAGE_BYTES;
        cp_wait1();          // stage jt fully arrived (jt+1 may be in flight)
        __syncthreads();

        // ---- S = Q K^T : single fp16 term ----
        float S[8][4];
        #pragma unroll
        for (int i = 0; i < 8; i++)
            #pragma unroll
            for (int j = 0; j < 4; j++) S[i][j] = 0.f;

        #pragma unroll
        for (int kb8 = 0; kb8 < 8; kb8++) {
            #pragma unroll
            for (int ntp = 0; ntp < 4; ntp++) {
                uint32_t a = smb + stg + (uint32_t)(ntp * 16 * PITCH + kb8 * 32)
                             + k_laneoff;
                uint32_t bp[4];
                ldsm_x4(bp, a);
                mma_fp16(S[2*ntp],   Qf[kb8], bp[0], bp[1]);
                mma_fp16(S[2*ntp+1], Qf[kb8], bp[2], bp[3]);
            }
        }

        // ---- log2-logits + mask + row max (needs full row) ----
        const bool diag = (jt == iq);
        const float* sksq = sksq0 + (jt & 1) * 64;
        float mxa = -3e30f, mxb = -3e30f;
        #pragma unroll
        for (int nt = 0; nt < 8; nt++) {
            int n0  = nt * 8 + 2 * tig;
            float ks0 = sksq[n0], ks1 = sksq[n0 + 1];
            int cg = jt * BN + n0;
            float a0 = fmaf(C2, S[nt][0], -(q2a + ks0));
            float a1 = fmaf(C2, S[nt][1], -(q2a + ks1));
            float c0 = fmaf(C2, S[nt][2], -(q2b + ks0));
            float c1 = fmaf(C2, S[nt][3], -(q2b + ks1));
            if (diag) {
                if (cg     > rA) a0 = -3e30f;
                if (cg + 1 > rA) a1 = -3e30f;
                if (cg     > rB) c0 = -3e30f;
                if (cg + 1 > rB) c1 = -3e30f;
            }
            S[nt][0] = a0; S[nt][1] = a1; S[nt][2] = c0; S[nt][3] = c1;
            mxa = fmaxf(mxa, fmaxf(a0, a1));
            mxb = fmaxf(mxb, fmaxf(c0, c1));
        }
        mxa = fmaxf(mxa, __shfl_xor_sync(0xffffffffu, mxa, 1));
        mxa = fmaxf(mxa, __shfl_xor_sync(0xffffffffu, mxa, 2));
        mxb = fmaxf(mxb, __shfl_xor_sync(0xffffffffu, mxb, 1));
        mxb = fmaxf(mxb, __shfl_xor_sync(0xffffffffu, mxb, 2));

        // ---- update bias, rescale O if it grew ----
        float bna = fmaxf(b_a, mxa - 14.f);
        if (bna > b_a) {
            float f = ex2(b_a - bna);
            #pragma unroll
            for (int dt = 0; dt < 16; dt++) { O[dt][0] *= f; O[dt][1] *= f; }
            b_a = bna;
        }
        float bnb = fmaxf(b_b, mxb - 14.f);
        if (bnb > b_b) {
            float f = ex2(b_b - bnb);
            #pragma unroll
            for (int dt = 0; dt < 16; dt++) { O[dt][2] *= f; O[dt][3] *= f; }
            b_b = bnb;
        }

        // ---- fused: per 16-col chunk, exp -> fp16 P frag -> PV MMAs.
        //      MUFU (next chunk's exp) overlaps the tensor pipe (this chunk). ----
        #pragma unroll
        for (int kj = 0; kj < 4; kj++) {
            uint32_t Pf[4];
            #pragma unroll
            for (int h = 0; h < 2; h++) {
                int nt = kj * 2 + h;
                float p0 = ex2(S[nt][0] - b_a);
                float p1 = ex2(S[nt][1] - b_a);
                float p2 = ex2(S[nt][2] - b_b);
                float p3 = ex2(S[nt][3] - b_b);
                __half2 ha = __floats2half2_rn(p0, p1);
                __half2 hb = __floats2half2_rn(p2, p3);
                Pf[h * 2]     = *(uint32_t*)&ha;
                Pf[h * 2 + 1] = *(uint32_t*)&hb;
            }
            #pragma unroll
            for (int dtp = 0; dtp < 8; dtp++) {
                uint32_t a = smb + stg + OFF_V
                             + (uint32_t)(kj * 16 * PITCH + dtp * 32) + v_laneoff;
                uint32_t vp[4];
                ldsm_x4_t(vp, a);
                mma_fp16(O[2*dtp],   Pf, vp[0], vp[1]);
                mma_fp16(O[2*dtp+1], Pf, vp[2], vp[3]);
            }
        }

        __syncthreads();                 // all warps done reading stage jt
        issue_KV(jt + 2);                // refill this stage (empty commit off-end)
    }

    // ---- epilogue: descale (O_true = O * 2^b) and store ----
    const float fa = ex2(b_a);
    const float fb = ex2(b_b);
    float* ob = gout + (size_t)bh * NSEQ * DDIM;
    float* oA = ob + (size_t)rA * DDIM;
    float* oB = ob + (size_t)rB * DDIM;
    #pragma unroll
    for (int dt = 0; dt < 16; dt++) {
        int c = dt * 8 + 2 * tig;
        *(float2*)(oA + c) = make_float2(O[dt][0] * fa, O[dt][1] * fa);
        *(float2*)(oB + c) = make_float2(O[dt][2] * fb, O[dt][3] * fb);
    }
}

extern "C" void kernel_launch(void* const* d_in, const int* in_sizes, int n_in,
                              void* d_out, int out_size) {
    const float* q = (const float*)d_in[0];
    const float* k = (const float*)d_in[1];
    const float* v = (const float*)d_in[2];
    float* out = (float*)d_out;

    prepass<<<NROWS / 8, 256>>>(q, k, v);

    cudaFuncSetAttribute(rbf_attn_hmma,
                         cudaFuncAttributeMaxDynamicSharedMemorySize, SMEM_BYTES);
    dim3 grid(NSEQ / BM, NBH);   // 32 q-tiles x 32 (b,h)
    rbf_attn_hmma<<<grid, 128, SMEM_BYTES>>>(out);
}